// round 4
// baseline (speedup 1.0000x reference)
#include <cuda_runtime.h>
#include <math.h>

#define BB   2
#define SS   1024
#define CSd  768
#define CZd  128
#define Dd   32
#define Hd   24
#define EPSf 1e-5f
#define NEG_INF (-1e9f)

// ---------------- scratch (static device globals; no allocation) ----------------
__device__ float g_emb[BB * 3 * CSd];                 // adaLN shift|scale|gate
__device__ float g_bsnorm[BB * SS * CSd];             // modulated LN(bs)
__device__ float g_q[BB * SS * CSd];                  // [b][s][h*D+d]
__device__ float g_k[BB * SS * CSd];
__device__ float g_v[BB * SS * CSd];
__device__ float g_attno[BB * SS * CSd];              // attention output pre-proj
__device__ float g_bias[(size_t)Hd * SS * SS];        // [h][i][j]  (100MB)

__inline__ __device__ float warp_sum(float v) {
    #pragma unroll
    for (int o = 16; o > 0; o >>= 1) v += __shfl_xor_sync(0xffffffffu, v, o);
    return v;
}
__inline__ __device__ float warp_max(float v) {
    #pragma unroll
    for (int o = 16; o > 0; o >>= 1) v = fmaxf(v, __shfl_xor_sync(0xffffffffu, v, o));
    return v;
}

// ---------------- 1) adaLN embedding: emb = silu(t) @ w_adaln + b_adaln ----------------
// grid (18, B), block 128; each thread one output column
__global__ void k_adaln(const float* __restrict__ t, const float* __restrict__ w,
                        const float* __restrict__ bb) {
    __shared__ float st[CSd];
    int b = blockIdx.y;
    for (int i = threadIdx.x; i < CSd; i += blockDim.x) {
        float x = t[b * CSd + i];
        st[i] = x / (1.0f + __expf(-x));
    }
    __syncthreads();
    int j = blockIdx.x * blockDim.x + threadIdx.x;   // < 2304
    float acc = bb[j];
    for (int i = 0; i < CSd; i++) acc += st[i] * w[i * 3 * CSd + j];
    g_emb[b * 3 * CSd + j] = acc;
}

// ---------------- 2) bs_norm = LN(bs)*(1+scale) + shift ----------------
// grid 2048 (one row), block 256
__global__ void k_bsnorm(const float* __restrict__ bs) {
    int row = blockIdx.x;            // b*S + s
    int b = row >> 10;
    const float* x = bs + (size_t)row * CSd;
    int t = threadIdx.x, w = t >> 5, lane = t & 31;
    float s1 = 0.f, s2 = 0.f;
    for (int c = t; c < CSd; c += 256) { float v = x[c]; s1 += v; s2 += v * v; }
    s1 = warp_sum(s1); s2 = warp_sum(s2);
    __shared__ float r1[8], r2[8], smu, srs;
    if (lane == 0) { r1[w] = s1; r2[w] = s2; }
    __syncthreads();
    if (t == 0) {
        float a = 0.f, c2 = 0.f;
        for (int i = 0; i < 8; i++) { a += r1[i]; c2 += r2[i]; }
        float mu = a * (1.0f / CSd);
        float var = c2 * (1.0f / CSd) - mu * mu;
        smu = mu; srs = rsqrtf(var + EPSf);
    }
    __syncthreads();
    float mu = smu, rs = srs;
    const float* eb = g_emb + b * 3 * CSd;
    float* outr = g_bsnorm + (size_t)row * CSd;
    for (int c = t; c < CSd; c += 256) {
        float sc = eb[CSd + c];     // scale
        float sh = eb[c];           // shift
        outr[c] = (x[c] - mu) * rs * (1.0f + sc) + sh;
    }
}

// ---------------- 3) QKV GEMM (fp32 128x128x8, 8x8/thread) ----------------
// grid (6, 16, 3), block 256.  C = g_bsnorm(2048x768) @ W(768x768)
__global__ void k_gemm_qkv(const float* __restrict__ wq, const float* __restrict__ wk,
                           const float* __restrict__ wv) {
    __shared__ float As[8][128];
    __shared__ float Bs[8][128];
    const float* W = (blockIdx.z == 0) ? wq : (blockIdx.z == 1) ? wk : wv;
    float* C = (blockIdx.z == 0) ? g_q : (blockIdx.z == 1) ? g_k : g_v;
    const float* A = g_bsnorm;
    int t = threadIdx.x;
    int m0 = blockIdx.y * 128, n0 = blockIdx.x * 128;
    int arow = t >> 1, acol = (t & 1) * 4;
    int brow = t >> 5, bcol = (t & 31) * 4;
    int ty = t >> 4, tx = t & 15;
    float acc[8][8];
    #pragma unroll
    for (int i = 0; i < 8; i++)
        #pragma unroll
        for (int j = 0; j < 8; j++) acc[i][j] = 0.f;

    for (int k0 = 0; k0 < CSd; k0 += 8) {
        float4 av = *(const float4*)&A[(size_t)(m0 + arow) * CSd + k0 + acol];
        float4 bv = *(const float4*)&W[(size_t)(k0 + brow) * CSd + n0 + bcol];
        __syncthreads();
        As[acol + 0][arow] = av.x; As[acol + 1][arow] = av.y;
        As[acol + 2][arow] = av.z; As[acol + 3][arow] = av.w;
        *(float4*)&Bs[brow][bcol] = bv;
        __syncthreads();
        #pragma unroll
        for (int kk = 0; kk < 8; kk++) {
            float4 a0 = *(float4*)&As[kk][ty * 8];
            float4 a1 = *(float4*)&As[kk][ty * 8 + 4];
            float4 b0 = *(float4*)&Bs[kk][tx * 8];
            float4 b1 = *(float4*)&Bs[kk][tx * 8 + 4];
            float ar[8] = {a0.x, a0.y, a0.z, a0.w, a1.x, a1.y, a1.z, a1.w};
            float br[8] = {b0.x, b0.y, b0.z, b0.w, b1.x, b1.y, b1.z, b1.w};
            #pragma unroll
            for (int i = 0; i < 8; i++)
                #pragma unroll
                for (int j = 0; j < 8; j++) acc[i][j] += ar[i] * br[j];
        }
    }
    #pragma unroll
    for (int i = 0; i < 8; i++) {
        size_t off = (size_t)(m0 + ty * 8 + i) * CSd + n0 + tx * 8;
        float4 v0 = {acc[i][0], acc[i][1], acc[i][2], acc[i][3]};
        float4 v1 = {acc[i][4], acc[i][5], acc[i][6], acc[i][7]};
        *(float4*)&C[off] = v0;
        *(float4*)&C[off + 4] = v1;
    }
}

// ---------------- 4) RMS norm on q (with 1/sqrt(D)) and k ----------------
// one warp per 32-chunk; grid 12288, block 256
__global__ void k_rms(const float* __restrict__ rqw, const float* __restrict__ rkw) {
    int gw = (blockIdx.x * blockDim.x + threadIdx.x) >> 5;
    int lane = threadIdx.x & 31;
    int which = (gw >= BB * SS * Hd);
    int idx = which ? gw - BB * SS * Hd : gw;
    float* ptr = (which ? g_k : g_q) + (size_t)idx * Dd;
    float x = ptr[lane];
    float ss = warp_sum(x * x);
    float r = rsqrtf(ss * (1.0f / Dd) + EPSf);
    float wv = (which ? rkw : rqw)[lane];
    float sc = which ? 1.0f : 0.17677669529663687f;   // 1/sqrt(32) folded into q
    ptr[lane] = x * r * wv * sc;
}

// ---------------- 5) bias[h][i][j] = LN(z[i,j]) @ w_z + mask ----------------
// 256 flattened (i,j) pairs per block; dynamic smem; 4 pairs x 6 heads per thread
#define BIAS_SMEM_FLOATS (256 * 129 + 128 * 24 + 24 + 24 + 256 + 256)
__global__ void k_bias(const float* __restrict__ z, const int* __restrict__ z_mask,
                       const float* __restrict__ lnw, const float* __restrict__ lnb,
                       const float* __restrict__ wz) {
    extern __shared__ float sm[];
    float* zs  = sm;                         // [256][129]
    float* wzl = zs + 256 * 129;             // [128][24]
    float* Ah  = wzl + 128 * 24;             // [24]
    float* Bh  = Ah + 24;                    // [24]
    float* mus = Bh + 24;                    // [256]
    float* rsg = mus + 256;                  // [256]
    int t = threadIdx.x;

    for (int idx = t; idx < 128 * 24; idx += 256) {
        int c = idx / 24;
        wzl[idx] = lnw[c] * wz[idx];         // wz is [c][h] row-major, idx == c*24+h
    }
    if (t < 24) {
        float a = 0.f, bsum = 0.f;
        for (int c = 0; c < 128; c++) {
            float wv = wz[c * 24 + t];
            a += lnw[c] * wv; bsum += lnb[c] * wv;
        }
        Ah[t] = a; Bh[t] = bsum;
    }
    size_t pair0 = (size_t)blockIdx.x * 256;
    const float4* zsrc = (const float4*)(z + pair0 * 128);
    for (int idx = t; idx < 256 * 32; idx += 256) {
        int p = idx >> 5, c4 = (idx & 31) * 4;
        float4 v = zsrc[idx];
        float* d = &zs[p * 129 + c4];
        d[0] = v.x; d[1] = v.y; d[2] = v.z; d[3] = v.w;
    }
    __syncthreads();

    // per-pair mean / rstd (thread t handles pair t)
    {
        float s1 = 0.f, s2 = 0.f;
        const float* zr = &zs[t * 129];
        for (int c = 0; c < 128; c++) { float v = zr[c]; s1 += v; s2 += v * v; }
        float mu = s1 * (1.0f / 128.0f);
        float var = s2 * (1.0f / 128.0f) - mu * mu;
        mus[t] = mu;
        rsg[t] = rsqrtf(var + EPSf);
    }
    __syncthreads();

    int pg = t & 63;         // base pair (lane-consecutive -> conflict-free)
    int hg = t >> 6;         // 0..3
    int h0 = hg * 6;
    float acc0[6], acc1[6], acc2[6], acc3[6];
    #pragma unroll
    for (int u = 0; u < 6; u++) { acc0[u] = acc1[u] = acc2[u] = acc3[u] = 0.f; }
    const float* wp = wzl + h0;
    #pragma unroll 4
    for (int c = 0; c < 128; c++) {
        float z0 = zs[(pg      ) * 129 + c];
        float z1 = zs[(pg +  64) * 129 + c];
        float z2 = zs[(pg + 128) * 129 + c];
        float z3 = zs[(pg + 192) * 129 + c];
        #pragma unroll
        for (int u = 0; u < 6; u++) {
            float wv = wp[c * 24 + u];
            acc0[u] += z0 * wv; acc1[u] += z1 * wv;
            acc2[u] += z2 * wv; acc3[u] += z3 * wv;
        }
    }
    int i_row = (int)(pair0 >> 10);
    int j0 = (int)(pair0 & 1023);
    #pragma unroll
    for (int k = 0; k < 4; k++) {
        int p = pg + 64 * k;
        int j = j0 + p;
        float mu = mus[p], rs = rsg[p];
        float mb = (z_mask[i_row * SS + j] != 0) ? 0.0f : NEG_INF;
        float* accp = (k == 0) ? acc0 : (k == 1) ? acc1 : (k == 2) ? acc2 : acc3;
        #pragma unroll
        for (int u = 0; u < 6; u++) {
            int h = h0 + u;
            float v = (accp[u] - mu * Ah[h]) * rs + Bh[h] + mb;
            g_bias[(size_t)h * SS * SS + (size_t)i_row * SS + j] = v;
        }
    }
}

// ---------------- 6) flash attention per (b, h, 64-row q tile) ----------------
// grid (16, 24, 2), block 256 (8 warps x 8 rows)
__global__ void k_attn(const float* __restrict__ beta) {
    __shared__ float Qs[64][33];
    __shared__ float Ks[64][33];
    __shared__ float Vs[64][33];
    __shared__ float Ps[64][64];
    int qt = blockIdx.x, h = blockIdx.y, b = blockIdx.z;
    int t = threadIdx.x, w = t >> 5, lane = t & 31;

    const float* qb = g_q + ((size_t)(b * SS) + qt * 64) * CSd + h * Dd;
    for (int idx = t; idx < 512; idx += 256) {
        int r = idx >> 3, f = (idx & 7) * 4;
        float4 v = *(const float4*)&qb[(size_t)r * CSd + f];
        Qs[r][f] = v.x; Qs[r][f + 1] = v.y; Qs[r][f + 2] = v.z; Qs[r][f + 3] = v.w;
    }

    float m8[8], l8[8], O8[8];
    #pragma unroll
    for (int r = 0; r < 8; r++) { m8[r] = -1e30f; l8[r] = 0.f; O8[r] = 0.f; }

    const float* bias_b = g_bias + ((size_t)h << 20);
    const float* beta_b = beta + ((size_t)b << 20);

    for (int kt = 0; kt < 16; kt++) {
        __syncthreads();
        const float* kb = g_k + ((size_t)(b * SS) + kt * 64) * CSd + h * Dd;
        const float* vb = g_v + ((size_t)(b * SS) + kt * 64) * CSd + h * Dd;
        for (int idx = t; idx < 512; idx += 256) {
            int r = idx >> 3, f = (idx & 7) * 4;
            float4 kv = *(const float4*)&kb[(size_t)r * CSd + f];
            float4 vv = *(const float4*)&vb[(size_t)r * CSd + f];
            Ks[r][f] = kv.x; Ks[r][f + 1] = kv.y; Ks[r][f + 2] = kv.z; Ks[r][f + 3] = kv.w;
            Vs[r][f] = vv.x; Vs[r][f + 1] = vv.y; Vs[r][f + 2] = vv.z; Vs[r][f + 3] = vv.w;
        }
        __syncthreads();

        #pragma unroll
        for (int r = 0; r < 8; r++) {
            int i = (w << 3) + r;
            int qi = qt * 64 + i;
            const float* bp = bias_b + (size_t)qi * SS + (kt << 6);
            const float* tp = beta_b + (size_t)qi * SS + (kt << 6);
            float bv1 = bp[lane], bv2 = bp[lane + 32];
            float tv1 = tp[lane], tv2 = tp[lane + 32];
            float s1 = 0.f, s2 = 0.f;
            #pragma unroll 8
            for (int kk = 0; kk < 32; kk++) {
                float qv = Qs[i][kk];
                s1 += qv * Ks[lane][kk];
                s2 += qv * Ks[lane + 32][kk];
            }
            s1 += bv1 + tv1;
            s2 += bv2 + tv2;
            float mx = warp_max(fmaxf(s1, s2));
            float newm = fmaxf(m8[r], mx);
            float corr = __expf(m8[r] - newm);
            float p1 = __expf(s1 - newm);
            float p2 = __expf(s2 - newm);
            float rs = warp_sum(p1 + p2);
            l8[r] = l8[r] * corr + rs;
            m8[r] = newm;
            Ps[i][lane] = p1;
            Ps[i][lane + 32] = p2;
            __syncwarp();
            float o = O8[r] * corr;
            #pragma unroll 8
            for (int j = 0; j < 64; j++) o += Ps[i][j] * Vs[j][lane];
            O8[r] = o;
        }
    }
    #pragma unroll
    for (int r = 0; r < 8; r++) {
        int i = (w << 3) + r;
        int qi = qt * 64 + i;
        g_attno[((size_t)(b * SS) + qi) * CSd + h * Dd + lane] = O8[r] / l8[r];
    }
}

// ---------------- 7) out projection + bias + gate ----------------
// grid (6, 16), block 256.  out = (g_attno @ w_o + b_o) * gate
__global__ void k_gemm_out(const float* __restrict__ wo, const float* __restrict__ bo,
                           float* __restrict__ out) {
    __shared__ float As[8][128];
    __shared__ float Bs[8][128];
    const float* A = g_attno;
    int t = threadIdx.x;
    int m0 = blockIdx.y * 128, n0 = blockIdx.x * 128;
    int arow = t >> 1, acol = (t & 1) * 4;
    int brow = t >> 5, bcol = (t & 31) * 4;
    int ty = t >> 4, tx = t & 15;
    float acc[8][8];
    #pragma unroll
    for (int i = 0; i < 8; i++)
        #pragma unroll
        for (int j = 0; j < 8; j++) acc[i][j] = 0.f;

    for (int k0 = 0; k0 < CSd; k0 += 8) {
        float4 av = *(const float4*)&A[(size_t)(m0 + arow) * CSd + k0 + acol];
        float4 bv = *(const float4*)&wo[(size_t)(k0 + brow) * CSd + n0 + bcol];
        __syncthreads();
        As[acol + 0][arow] = av.x; As[acol + 1][arow] = av.y;
        As[acol + 2][arow] = av.z; As[acol + 3][arow] = av.w;
        *(float4*)&Bs[brow][bcol] = bv;
        __syncthreads();
        #pragma unroll
        for (int kk = 0; kk < 8; kk++) {
            float4 a0 = *(float4*)&As[kk][ty * 8];
            float4 a1 = *(float4*)&As[kk][ty * 8 + 4];
            float4 b0 = *(float4*)&Bs[kk][tx * 8];
            float4 b1 = *(float4*)&Bs[kk][tx * 8 + 4];
            float ar[8] = {a0.x, a0.y, a0.z, a0.w, a1.x, a1.y, a1.z, a1.w};
            float br[8] = {b0.x, b0.y, b0.z, b0.w, b1.x, b1.y, b1.z, b1.w};
            #pragma unroll
            for (int i = 0; i < 8; i++)
                #pragma unroll
                for (int j = 0; j < 8; j++) acc[i][j] += ar[i] * br[j];
        }
    }
    #pragma unroll
    for (int i = 0; i < 8; i++) {
        int m = m0 + ty * 8 + i;
        int bidx = m >> 10;
        const float* gate = g_emb + bidx * 3 * CSd + 2 * CSd;
        float vals[8];
        #pragma unroll
        for (int j = 0; j < 8; j++) {
            int n = n0 + tx * 8 + j;
            vals[j] = (acc[i][j] + bo[n]) * gate[n];
        }
        size_t off = (size_t)m * CSd + n0 + tx * 8;
        float4 v0 = {vals[0], vals[1], vals[2], vals[3]};
        float4 v1 = {vals[4], vals[5], vals[6], vals[7]};
        *(float4*)&out[off] = v0;
        *(float4*)&out[off + 4] = v1;
    }
}

// ---------------- launch ----------------
extern "C" void kernel_launch(void* const* d_in, const int* in_sizes, int n_in,
                              void* d_out, int out_size) {
    const float* bs      = (const float*)d_in[0];
    const float* z       = (const float*)d_in[1];
    const float* t       = (const float*)d_in[2];
    const float* beta    = (const float*)d_in[3];
    const int*   z_mask  = (const int*)d_in[4];
    const float* w_adaln = (const float*)d_in[5];
    const float* b_adaln = (const float*)d_in[6];
    const float* ln_z_w  = (const float*)d_in[7];
    const float* ln_z_b  = (const float*)d_in[8];
    const float* w_q     = (const float*)d_in[9];
    const float* w_k     = (const float*)d_in[10];
    const float* w_v     = (const float*)d_in[11];
    const float* w_z     = (const float*)d_in[12];
    const float* rms_q_w = (const float*)d_in[13];
    const float* rms_k_w = (const float*)d_in[14];
    const float* w_o     = (const float*)d_in[15];
    const float* b_o     = (const float*)d_in[16];
    float* out = (float*)d_out;

    (void)cudaFuncSetAttribute(k_bias, cudaFuncAttributeMaxDynamicSharedMemorySize,
                               BIAS_SMEM_FLOATS * (int)sizeof(float));

    k_adaln<<<dim3(18, 2), 128>>>(t, w_adaln, b_adaln);
    k_bsnorm<<<BB * SS, 256>>>(bs);
    k_gemm_qkv<<<dim3(6, 16, 3), 256>>>(w_q, w_k, w_v);
    k_rms<<<12288, 256>>>(rms_q_w, rms_k_w);
    k_bias<<<4096, 256, BIAS_SMEM_FLOATS * (int)sizeof(float)>>>(z, z_mask, ln_z_w, ln_z_b, w_z);
    k_attn<<<dim3(16, 24, 2), 256>>>(beta);
    k_gemm_out<<<dim3(6, 16), 256>>>(w_o, b_o, out);
}

// round 5
// speedup vs baseline: 3.0014x; 3.0014x over previous
#include <cuda_runtime.h>
#include <math.h>
#include <stdint.h>

#define BB   2
#define SS   1024
#define CSd  768
#define CZd  128
#define Dd   32
#define Hd   24
#define EPSf 1e-5f
#define NEG_INF (-1e9f)

// ---------------- scratch (static device globals; no allocation) ----------------
__device__ float g_emb[BB * 3 * CSd];                 // adaLN shift|scale|gate
__device__ float g_bsnorm[BB * SS * CSd];             // modulated LN(bs)
__device__ float g_q[BB * SS * CSd];                  // [b][s][h*D+d]
__device__ float g_k[BB * SS * CSd];
__device__ float g_v[BB * SS * CSd];
__device__ float g_attno[BB * SS * CSd];              // attention output pre-proj
__device__ float g_bias[(size_t)Hd * SS * SS];        // [h][i][j]  (100MB)

__inline__ __device__ float warp_sum(float v) {
    #pragma unroll
    for (int o = 16; o > 0; o >>= 1) v += __shfl_xor_sync(0xffffffffu, v, o);
    return v;
}

__device__ __forceinline__ float to_tf32(float x) {
    uint32_t u;
    asm("cvt.rna.tf32.f32 %0, %1;" : "=r"(u) : "f"(x));
    return __uint_as_float(u);
}

__device__ __forceinline__ void mma_tf32(float c[4], uint32_t a0, uint32_t a1,
                                         uint32_t a2, uint32_t a3,
                                         uint32_t b0, uint32_t b1) {
    asm volatile(
        "mma.sync.aligned.m16n8k8.row.col.f32.tf32.tf32.f32 "
        "{%0,%1,%2,%3}, {%4,%5,%6,%7}, {%8,%9}, {%0,%1,%2,%3};"
        : "+f"(c[0]), "+f"(c[1]), "+f"(c[2]), "+f"(c[3])
        : "r"(a0), "r"(a1), "r"(a2), "r"(a3), "r"(b0), "r"(b1));
}

#define FBITS(x) __float_as_uint(x)

// ---------------- 1) adaLN embedding ----------------
__global__ void k_adaln(const float* __restrict__ t, const float* __restrict__ w,
                        const float* __restrict__ bb) {
    __shared__ float st[CSd];
    int b = blockIdx.y;
    for (int i = threadIdx.x; i < CSd; i += blockDim.x) {
        float x = t[b * CSd + i];
        st[i] = x / (1.0f + __expf(-x));
    }
    __syncthreads();
    int j = blockIdx.x * blockDim.x + threadIdx.x;   // < 2304
    float acc = bb[j];
    for (int i = 0; i < CSd; i++) acc += st[i] * w[i * 3 * CSd + j];
    g_emb[b * 3 * CSd + j] = acc;
}

// ---------------- 2) bs_norm = LN(bs)*(1+scale) + shift ----------------
__global__ void k_bsnorm(const float* __restrict__ bs) {
    int row = blockIdx.x;            // b*S + s
    int b = row >> 10;
    const float* x = bs + (size_t)row * CSd;
    int t = threadIdx.x, w = t >> 5, lane = t & 31;
    float s1 = 0.f, s2 = 0.f;
    for (int c = t; c < CSd; c += 256) { float v = x[c]; s1 += v; s2 += v * v; }
    s1 = warp_sum(s1); s2 = warp_sum(s2);
    __shared__ float r1[8], r2[8], smu, srs;
    if (lane == 0) { r1[w] = s1; r2[w] = s2; }
    __syncthreads();
    if (t == 0) {
        float a = 0.f, c2 = 0.f;
        for (int i = 0; i < 8; i++) { a += r1[i]; c2 += r2[i]; }
        float mu = a * (1.0f / CSd);
        float var = c2 * (1.0f / CSd) - mu * mu;
        smu = mu; srs = rsqrtf(var + EPSf);
    }
    __syncthreads();
    float mu = smu, rs = srs;
    const float* eb = g_emb + b * 3 * CSd;
    float* outr = g_bsnorm + (size_t)row * CSd;
    for (int c = t; c < CSd; c += 256) {
        float sc = eb[CSd + c];
        float sh = eb[c];
        outr[c] = (x[c] - mu) * rs * (1.0f + sc) + sh;
    }
}

// ---------------- 3) QKV GEMM (tf32 mma, 128x128 tiles) ----------------
// grid (6, 16, 3), block 256.
__global__ __launch_bounds__(256) void k_gemm_qkv(const float* __restrict__ wq,
                                                  const float* __restrict__ wk,
                                                  const float* __restrict__ wv) {
    __shared__ float As[128 * 20];    // stride 20 (== 4 mod 32)
    __shared__ float Ws[16 * 136];    // stride 136 (== 8 mod 32)
    const float* W = (blockIdx.z == 0) ? wq : (blockIdx.z == 1) ? wk : wv;
    float* C = (blockIdx.z == 0) ? g_q : (blockIdx.z == 1) ? g_k : g_v;
    const float* A = g_bsnorm;
    int t = threadIdx.x, w = t >> 5, lane = t & 31;
    int lg = lane >> 2, lr = lane & 3;
    int m0 = blockIdx.y * 128, n0 = blockIdx.x * 128;
    int wm = (w & 3) * 32, wn = (w >> 2) * 64;
    float acc[2][8][4];
    #pragma unroll
    for (int mt = 0; mt < 2; mt++)
        #pragma unroll
        for (int nt = 0; nt < 8; nt++)
            #pragma unroll
            for (int j = 0; j < 4; j++) acc[mt][nt][j] = 0.f;

    for (int k0 = 0; k0 < CSd; k0 += 16) {
        __syncthreads();
        #pragma unroll
        for (int idx = t; idx < 512; idx += 256) {
            int r = idx >> 2, c4 = (idx & 3) * 4;
            float4 v = *(const float4*)&A[(size_t)(m0 + r) * CSd + k0 + c4];
            float4 tv = {to_tf32(v.x), to_tf32(v.y), to_tf32(v.z), to_tf32(v.w)};
            *(float4*)&As[r * 20 + c4] = tv;
        }
        #pragma unroll
        for (int idx = t; idx < 512; idx += 256) {
            int r = idx >> 5, c4 = (idx & 31) * 4;
            float4 v = *(const float4*)&W[(size_t)(k0 + r) * CSd + n0 + c4];
            float4 tv = {to_tf32(v.x), to_tf32(v.y), to_tf32(v.z), to_tf32(v.w)};
            *(float4*)&Ws[r * 136 + c4] = tv;
        }
        __syncthreads();
        #pragma unroll
        for (int kc = 0; kc < 2; kc++) {
            uint32_t a[2][4];
            #pragma unroll
            for (int mt = 0; mt < 2; mt++) {
                const float* ap = &As[(wm + mt * 16 + lg) * 20 + kc * 8 + lr];
                a[mt][0] = FBITS(ap[0]);       a[mt][1] = FBITS(ap[8 * 20]);
                a[mt][2] = FBITS(ap[4]);       a[mt][3] = FBITS(ap[8 * 20 + 4]);
            }
            #pragma unroll
            for (int nt = 0; nt < 8; nt++) {
                const float* wp = &Ws[(kc * 8 + lr) * 136 + wn + nt * 8 + lg];
                uint32_t b0 = FBITS(wp[0]), b1 = FBITS(wp[4 * 136]);
                mma_tf32(acc[0][nt], a[0][0], a[0][1], a[0][2], a[0][3], b0, b1);
                mma_tf32(acc[1][nt], a[1][0], a[1][1], a[1][2], a[1][3], b0, b1);
            }
        }
    }
    #pragma unroll
    for (int mt = 0; mt < 2; mt++)
        #pragma unroll
        for (int nt = 0; nt < 8; nt++) {
            int row = m0 + wm + mt * 16 + lg;
            int col = n0 + wn + nt * 8 + 2 * lr;
            float2 v0 = {acc[mt][nt][0], acc[mt][nt][1]};
            float2 v1 = {acc[mt][nt][2], acc[mt][nt][3]};
            *(float2*)&C[(size_t)row * CSd + col] = v0;
            *(float2*)&C[(size_t)(row + 8) * CSd + col] = v1;
        }
}

// ---------------- 4) RMS norm on q (with 1/sqrt(D)) and k ----------------
__global__ void k_rms(const float* __restrict__ rqw, const float* __restrict__ rkw) {
    int gw = (blockIdx.x * blockDim.x + threadIdx.x) >> 5;
    int lane = threadIdx.x & 31;
    int which = (gw >= BB * SS * Hd);
    int idx = which ? gw - BB * SS * Hd : gw;
    float* ptr = (which ? g_k : g_q) + (size_t)idx * Dd;
    float x = ptr[lane];
    float ss = warp_sum(x * x);
    float r = rsqrtf(ss * (1.0f / Dd) + EPSf);
    float wv = (which ? rkw : rqw)[lane];
    float sc = which ? 1.0f : 0.17677669529663687f;   // 1/sqrt(32) folded into q
    ptr[lane] = x * r * wv * sc;
}

// ---------------- 5) bias via tf32 mma: [256x128] @ [128x24] per CTA ----------------
#define BIAS_SM_FLOATS (256 * 68 + 128 * 40 + 256 * 3 + 48)
__global__ __launch_bounds__(256, 2) void k_bias(const float* __restrict__ z,
                                                 const int* __restrict__ z_mask,
                                                 const float* __restrict__ lnw,
                                                 const float* __restrict__ lnb,
                                                 const float* __restrict__ wz) {
    extern __shared__ float sb[];
    float* zs  = sb;                 // [256][68]   stride 68 (==4 mod 32)
    float* wzs = zs + 256 * 68;      // [128][40]   stride 40 (==8 mod 32)
    float* mus = wzs + 128 * 40;     // [256]
    float* rsg = mus + 256;          // [256]
    float* mbs = rsg + 256;          // [256]
    float* Ah  = mbs + 256;          // [24]
    float* Bh  = Ah + 24;            // [24]
    int t = threadIdx.x, w = t >> 5, lane = t & 31;
    int lg = lane >> 2, lr = lane & 3;
    int wr = w * 32;
    size_t pair0 = (size_t)blockIdx.x * 256;
    int i_row = (int)(pair0 >> 10);
    int j0 = (int)(pair0 & 1023);

    for (int idx = t; idx < 128 * 24; idx += 256) {
        int k = idx / 24, hh = idx - k * 24;
        wzs[k * 40 + hh] = to_tf32(lnw[k] * wz[idx]);
    }
    if (t < 24) {
        float a = 0.f, bsum = 0.f;
        for (int c = 0; c < 128; c++) {
            float wv = wz[c * 24 + t];
            a += lnw[c] * wv; bsum += lnb[c] * wv;
        }
        Ah[t] = a; Bh[t] = bsum;
    }
    mbs[t] = (z_mask[i_row * SS + j0 + t] != 0) ? 0.0f : NEG_INF;

    float acc[2][3][4];
    #pragma unroll
    for (int mt = 0; mt < 2; mt++)
        #pragma unroll
        for (int nt = 0; nt < 3; nt++)
            #pragma unroll
            for (int j = 0; j < 4; j++) acc[mt][nt][j] = 0.f;

    float s1 = 0.f, s2 = 0.f;
    #pragma unroll
    for (int half = 0; half < 2; half++) {
        __syncthreads();
        #pragma unroll
        for (int idx = t; idx < 4096; idx += 256) {   // 256 pairs x 16 float4
            int p = idx >> 4, c4 = (idx & 15) * 4;
            float4 v = *(const float4*)&z[(pair0 + p) * 128 + half * 64 + c4];
            float4 tv = {to_tf32(v.x), to_tf32(v.y), to_tf32(v.z), to_tf32(v.w)};
            *(float4*)&zs[p * 68 + c4] = tv;
        }
        __syncthreads();
        {   // per-pair stats (thread t owns pair t)
            const float* zr = &zs[t * 68];
            for (int c = 0; c < 64; c++) { float v = zr[c]; s1 += v; s2 += v * v; }
        }
        if (half == 1) {
            float mu = s1 * (1.0f / 128.0f);
            float var = s2 * (1.0f / 128.0f) - mu * mu;
            mus[t] = mu; rsg[t] = rsqrtf(var + EPSf);
        }
        #pragma unroll
        for (int kc = 0; kc < 8; kc++) {
            uint32_t a[2][4];
            #pragma unroll
            for (int mt = 0; mt < 2; mt++) {
                const float* ap = &zs[(wr + mt * 16 + lg) * 68 + kc * 8 + lr];
                a[mt][0] = FBITS(ap[0]);     a[mt][1] = FBITS(ap[8 * 68]);
                a[mt][2] = FBITS(ap[4]);     a[mt][3] = FBITS(ap[8 * 68 + 4]);
            }
            #pragma unroll
            for (int nt = 0; nt < 3; nt++) {
                const float* wp = &wzs[(half * 64 + kc * 8 + lr) * 40 + nt * 8 + lg];
                uint32_t b0 = FBITS(wp[0]), b1 = FBITS(wp[4 * 40]);
                mma_tf32(acc[0][nt], a[0][0], a[0][1], a[0][2], a[0][3], b0, b1);
                mma_tf32(acc[1][nt], a[1][0], a[1][1], a[1][2], a[1][3], b0, b1);
            }
        }
    }
    __syncthreads();   // mus/rsg visible to all
    #pragma unroll
    for (int mt = 0; mt < 2; mt++)
        #pragma unroll
        for (int nt = 0; nt < 3; nt++) {
            int p0 = wr + mt * 16 + lg;
            int hh = nt * 8 + 2 * lr;
            #pragma unroll
            for (int half = 0; half < 2; half++) {
                int p = p0 + half * 8;
                float mu = mus[p], rs = rsg[p], mb = mbs[p];
                float v0 = (acc[mt][nt][2 * half + 0] - mu * Ah[hh]) * rs + Bh[hh] + mb;
                float v1 = (acc[mt][nt][2 * half + 1] - mu * Ah[hh + 1]) * rs + Bh[hh + 1] + mb;
                size_t base = (size_t)i_row * SS + j0 + p;
                g_bias[(size_t)hh * SS * SS + base] = v0;
                g_bias[(size_t)(hh + 1) * SS * SS + base] = v1;
            }
        }
}

// ---------------- 6) flash attention, tf32 mma, 128 q-rows/CTA ----------------
// grid (2, 24, 8): x=b (fastest, bias L2 reuse), y=h (beta L2 reuse), z=qt
#define ATTN_SM_FLOATS (128 * 36 + 64 * 36 + 64 * 40 + 128 * 68)
__global__ __launch_bounds__(256, 2) void k_attn(const float* __restrict__ beta) {
    extern __shared__ float sa[];
    float* Qs = sa;                   // [128][36]  (==4 mod 32)
    float* Ks = Qs + 128 * 36;        // [64][36]
    float* Vs = Ks + 64 * 36;         // [64][40]   (==8 mod 32)
    float* Ps = Vs + 64 * 40;         // [128][68]  bias+beta staging / P staging
    int b = blockIdx.x, h = blockIdx.y, qt = blockIdx.z;
    int t = threadIdx.x, w = t >> 5, lane = t & 31;
    int lg = lane >> 2, lr = lane & 3;
    int wr = w * 16;

    const float* qg = g_q + ((size_t)(b * SS + qt * 128)) * CSd + h * Dd;
    #pragma unroll
    for (int idx = t; idx < 128 * 8; idx += 256) {
        int r = idx >> 3, c4 = (idx & 7) * 4;
        float4 v = *(const float4*)&qg[(size_t)r * CSd + c4];
        float4 tv = {to_tf32(v.x), to_tf32(v.y), to_tf32(v.z), to_tf32(v.w)};
        *(float4*)&Qs[r * 36 + c4] = tv;
    }

    float O[4][4];
    #pragma unroll
    for (int dn = 0; dn < 4; dn++)
        #pragma unroll
        for (int j = 0; j < 4; j++) O[dn][j] = 0.f;
    float m0 = -1e30f, m1 = -1e30f, l0 = 0.f, l1 = 0.f;

    const float* bias_b = g_bias + ((size_t)h << 20) + (size_t)(qt * 128) * SS;
    const float* beta_b = beta + ((size_t)b << 20) + (size_t)(qt * 128) * SS;
    const float* kg = g_k + (size_t)(b * SS) * CSd + h * Dd;
    const float* vg = g_v + (size_t)(b * SS) * CSd + h * Dd;

    for (int kt = 0; kt < 16; kt++) {
        __syncthreads();
        #pragma unroll
        for (int idx = t; idx < 64 * 8; idx += 256) {
            int r = idx >> 3, c4 = (idx & 7) * 4;
            float4 kv = *(const float4*)&kg[(size_t)(kt * 64 + r) * CSd + c4];
            float4 vv = *(const float4*)&vg[(size_t)(kt * 64 + r) * CSd + c4];
            float4 tk = {to_tf32(kv.x), to_tf32(kv.y), to_tf32(kv.z), to_tf32(kv.w)};
            float4 tv = {to_tf32(vv.x), to_tf32(vv.y), to_tf32(vv.z), to_tf32(vv.w)};
            *(float4*)&Ks[r * 36 + c4] = tk;
            *(float4*)&Vs[r * 40 + c4] = tv;
        }
        #pragma unroll
        for (int idx = t; idx < 128 * 16; idx += 256) {
            int p = idx >> 4, c4 = (idx & 15) * 4;
            float4 b4 = *(const float4*)&bias_b[(size_t)p * SS + kt * 64 + c4];
            float4 t4 = *(const float4*)&beta_b[(size_t)p * SS + kt * 64 + c4];
            float4 s4 = {b4.x + t4.x, b4.y + t4.y, b4.z + t4.z, b4.w + t4.w};
            *(float4*)&Ps[p * 68 + c4] = s4;
        }
        __syncthreads();

        // ---- S = Q @ K^T ----
        uint32_t qa[4][4];
        #pragma unroll
        for (int kc = 0; kc < 4; kc++) {
            const float* qp = &Qs[(wr + lg) * 36 + kc * 8 + lr];
            qa[kc][0] = FBITS(qp[0]);      qa[kc][1] = FBITS(qp[8 * 36]);
            qa[kc][2] = FBITS(qp[4]);      qa[kc][3] = FBITS(qp[8 * 36 + 4]);
        }
        float S[8][4];
        #pragma unroll
        for (int nt = 0; nt < 8; nt++) {
            S[nt][0] = S[nt][1] = S[nt][2] = S[nt][3] = 0.f;
            #pragma unroll
            for (int kc = 0; kc < 4; kc++) {
                const float* kp = &Ks[(nt * 8 + lg) * 36 + kc * 8 + lr];
                uint32_t b0 = FBITS(kp[0]), b1 = FBITS(kp[4]);
                mma_tf32(S[nt], qa[kc][0], qa[kc][1], qa[kc][2], qa[kc][3], b0, b1);
            }
        }
        // ---- add bias+beta, online softmax (warp-local rows) ----
        float mp0 = -1e30f, mp1 = -1e30f;
        #pragma unroll
        for (int nt = 0; nt < 8; nt++) {
            const float* pb = &Ps[(wr + lg) * 68 + nt * 8 + 2 * lr];
            S[nt][0] += pb[0];          S[nt][1] += pb[1];
            S[nt][2] += pb[8 * 68];     S[nt][3] += pb[8 * 68 + 1];
            mp0 = fmaxf(mp0, fmaxf(S[nt][0], S[nt][1]));
            mp1 = fmaxf(mp1, fmaxf(S[nt][2], S[nt][3]));
        }
        mp0 = fmaxf(mp0, __shfl_xor_sync(0xffffffffu, mp0, 1));
        mp0 = fmaxf(mp0, __shfl_xor_sync(0xffffffffu, mp0, 2));
        mp1 = fmaxf(mp1, __shfl_xor_sync(0xffffffffu, mp1, 1));
        mp1 = fmaxf(mp1, __shfl_xor_sync(0xffffffffu, mp1, 2));
        float nm0 = fmaxf(m0, mp0), nm1 = fmaxf(m1, mp1);
        float c0 = __expf(m0 - nm0), c1 = __expf(m1 - nm1);
        m0 = nm0; m1 = nm1;
        float s0 = 0.f, s1 = 0.f;
        #pragma unroll
        for (int nt = 0; nt < 8; nt++) {
            S[nt][0] = __expf(S[nt][0] - nm0);
            S[nt][1] = __expf(S[nt][1] - nm0);
            S[nt][2] = __expf(S[nt][2] - nm1);
            S[nt][3] = __expf(S[nt][3] - nm1);
            s0 += S[nt][0] + S[nt][1];
            s1 += S[nt][2] + S[nt][3];
            float* pb = &Ps[(wr + lg) * 68 + nt * 8 + 2 * lr];
            pb[0] = to_tf32(S[nt][0]);          pb[1] = to_tf32(S[nt][1]);
            pb[8 * 68] = to_tf32(S[nt][2]);     pb[8 * 68 + 1] = to_tf32(S[nt][3]);
        }
        s0 += __shfl_xor_sync(0xffffffffu, s0, 1);
        s0 += __shfl_xor_sync(0xffffffffu, s0, 2);
        s1 += __shfl_xor_sync(0xffffffffu, s1, 1);
        s1 += __shfl_xor_sync(0xffffffffu, s1, 2);
        l0 = l0 * c0 + s0;
        l1 = l1 * c1 + s1;
        #pragma unroll
        for (int dn = 0; dn < 4; dn++) {
            O[dn][0] *= c0; O[dn][1] *= c0; O[dn][2] *= c1; O[dn][3] *= c1;
        }
        __syncwarp();
        // ---- O += P @ V ----
        #pragma unroll
        for (int kc = 0; kc < 8; kc++) {
            const float* pp = &Ps[(wr + lg) * 68 + kc * 8 + lr];
            uint32_t a0 = FBITS(pp[0]), a1 = FBITS(pp[8 * 68]);
            uint32_t a2 = FBITS(pp[4]), a3 = FBITS(pp[8 * 68 + 4]);
            #pragma unroll
            for (int dn = 0; dn < 4; dn++) {
                const float* vp = &Vs[(kc * 8 + lr) * 40 + dn * 8 + lg];
                uint32_t b0 = FBITS(vp[0]), b1 = FBITS(vp[4 * 40]);
                mma_tf32(O[dn], a0, a1, a2, a3, b0, b1);
            }
        }
    }
    // epilogue
    float inv0 = 1.0f / l0, inv1 = 1.0f / l1;
    float* og = g_attno + ((size_t)(b * SS + qt * 128)) * CSd + h * Dd;
    #pragma unroll
    for (int dn = 0; dn < 4; dn++) {
        int col = dn * 8 + 2 * lr;
        int r0 = wr + lg;
        float2 v0 = {O[dn][0] * inv0, O[dn][1] * inv0};
        float2 v1 = {O[dn][2] * inv1, O[dn][3] * inv1};
        *(float2*)&og[(size_t)r0 * CSd + col] = v0;
        *(float2*)&og[(size_t)(r0 + 8) * CSd + col] = v1;
    }
}

// ---------------- 7) out projection + bias + gate (tf32 mma) ----------------
// grid (6, 16), block 256
__global__ __launch_bounds__(256) void k_gemm_out(const float* __restrict__ wo,
                                                  const float* __restrict__ bo,
                                                  float* __restrict__ out) {
    __shared__ float As[128 * 20];
    __shared__ float Ws[16 * 136];
    const float* A = g_attno;
    int t = threadIdx.x, w = t >> 5, lane = t & 31;
    int lg = lane >> 2, lr = lane & 3;
    int m0 = blockIdx.y * 128, n0 = blockIdx.x * 128;
    int wm = (w & 3) * 32, wn = (w >> 2) * 64;
    float acc[2][8][4];
    #pragma unroll
    for (int mt = 0; mt < 2; mt++)
        #pragma unroll
        for (int nt = 0; nt < 8; nt++)
            #pragma unroll
            for (int j = 0; j < 4; j++) acc[mt][nt][j] = 0.f;

    for (int k0 = 0; k0 < CSd; k0 += 16) {
        __syncthreads();
        #pragma unroll
        for (int idx = t; idx < 512; idx += 256) {
            int r = idx >> 2, c4 = (idx & 3) * 4;
            float4 v = *(const float4*)&A[(size_t)(m0 + r) * CSd + k0 + c4];
            float4 tv = {to_tf32(v.x), to_tf32(v.y), to_tf32(v.z), to_tf32(v.w)};
            *(float4*)&As[r * 20 + c4] = tv;
        }
        #pragma unroll
        for (int idx = t; idx < 512; idx += 256) {
            int r = idx >> 5, c4 = (idx & 31) * 4;
            float4 v = *(const float4*)&wo[(size_t)(k0 + r) * CSd + n0 + c4];
            float4 tv = {to_tf32(v.x), to_tf32(v.y), to_tf32(v.z), to_tf32(v.w)};
            *(float4*)&Ws[r * 136 + c4] = tv;
        }
        __syncthreads();
        #pragma unroll
        for (int kc = 0; kc < 2; kc++) {
            uint32_t a[2][4];
            #pragma unroll
            for (int mt = 0; mt < 2; mt++) {
                const float* ap = &As[(wm + mt * 16 + lg) * 20 + kc * 8 + lr];
                a[mt][0] = FBITS(ap[0]);       a[mt][1] = FBITS(ap[8 * 20]);
                a[mt][2] = FBITS(ap[4]);       a[mt][3] = FBITS(ap[8 * 20 + 4]);
            }
            #pragma unroll
            for (int nt = 0; nt < 8; nt++) {
                const float* wp = &Ws[(kc * 8 + lr) * 136 + wn + nt * 8 + lg];
                uint32_t b0 = FBITS(wp[0]), b1 = FBITS(wp[4 * 136]);
                mma_tf32(acc[0][nt], a[0][0], a[0][1], a[0][2], a[0][3], b0, b1);
                mma_tf32(acc[1][nt], a[1][0], a[1][1], a[1][2], a[1][3], b0, b1);
            }
        }
    }
    #pragma unroll
    for (int mt = 0; mt < 2; mt++)
        #pragma unroll
        for (int nt = 0; nt < 8; nt++) {
            int row = m0 + wm + mt * 16 + lg;
            int col = n0 + wn + nt * 8 + 2 * lr;
            int bidx = row >> 10;   // row and row+8 stay in same 128-tile => same batch
            const float* gate = g_emb + bidx * 3 * CSd + 2 * CSd;
            float gb0 = gate[col], gb1 = gate[col + 1];
            float bb0 = bo[col], bb1 = bo[col + 1];
            float2 v0 = {(acc[mt][nt][0] + bb0) * gb0, (acc[mt][nt][1] + bb1) * gb1};
            float2 v1 = {(acc[mt][nt][2] + bb0) * gb0, (acc[mt][nt][3] + bb1) * gb1};
            *(float2*)&out[(size_t)row * CSd + col] = v0;
            *(float2*)&out[(size_t)(row + 8) * CSd + col] = v1;
        }
}

// ---------------- launch ----------------
extern "C" void kernel_launch(void* const* d_in, const int* in_sizes, int n_in,
                              void* d_out, int out_size) {
    const float* bs      = (const float*)d_in[0];
    const float* z       = (const float*)d_in[1];
    const float* t       = (const float*)d_in[2];
    const float* beta    = (const float*)d_in[3];
    const int*   z_mask  = (const int*)d_in[4];
    const float* w_adaln = (const float*)d_in[5];
    const float* b_adaln = (const float*)d_in[6];
    const float* ln_z_w  = (const float*)d_in[7];
    const float* ln_z_b  = (const float*)d_in[8];
    const float* w_q     = (const float*)d_in[9];
    const float* w_k     = (const float*)d_in[10];
    const float* w_v     = (const float*)d_in[11];
    const float* w_z     = (const float*)d_in[12];
    const float* rms_q_w = (const float*)d_in[13];
    const float* rms_k_w = (const float*)d_in[14];
    const float* w_o     = (const float*)d_in[15];
    const float* b_o     = (const float*)d_in[16];
    float* out = (float*)d_out;

    (void)cudaFuncSetAttribute(k_bias, cudaFuncAttributeMaxDynamicSharedMemorySize,
                               BIAS_SM_FLOATS * (int)sizeof(float));
    (void)cudaFuncSetAttribute(k_attn, cudaFuncAttributeMaxDynamicSharedMemorySize,
                               ATTN_SM_FLOATS * (int)sizeof(float));

    k_adaln<<<dim3(18, 2), 128>>>(t, w_adaln, b_adaln);
    k_bsnorm<<<BB * SS, 256>>>(bs);
    k_gemm_qkv<<<dim3(6, 16, 3), 256>>>(w_q, w_k, w_v);
    k_rms<<<12288, 256>>>(rms_q_w, rms_k_w);
    k_bias<<<4096, 256, BIAS_SM_FLOATS * (int)sizeof(float)>>>(z, z_mask, ln_z_w, ln_z_b, w_z);
    k_attn<<<dim3(2, 24, 8), 256, ATTN_SM_FLOATS * (int)sizeof(float)>>>(beta);
    k_gemm_out<<<dim3(6, 16), 256>>>(w_o, b_o, out);
}

// round 6
// speedup vs baseline: 3.0625x; 1.0204x over previous
#include <cuda_runtime.h>
#include <math.h>
#include <stdint.h>

#define BB   2
#define SS   1024
#define CSd  768
#define CZd  128
#define Dd   32
#define Hd   24
#define EPSf 1e-5f
#define NEG_INF (-1e9f)

// ---------------- scratch (static device globals; no allocation) ----------------
__device__ float g_emb[BB * 3 * CSd];                 // adaLN shift|scale|gate
__device__ float g_bsnorm[BB * SS * CSd];             // modulated LN(bs)
__device__ float g_q[BB * SS * CSd];                  // [b][s][h*D+d] (rms+scale folded)
__device__ float g_k[BB * SS * CSd];                  // (rms folded)
__device__ float g_v[BB * SS * CSd];
__device__ float g_attno[BB * SS * CSd];              // attention output pre-proj
__device__ float g_bias[(size_t)Hd * SS * SS];        // [h][i][j]  (100MB)

__inline__ __device__ float warp_sum(float v) {
    #pragma unroll
    for (int o = 16; o > 0; o >>= 1) v += __shfl_xor_sync(0xffffffffu, v, o);
    return v;
}

__device__ __forceinline__ float to_tf32(float x) {
    uint32_t u;
    asm("cvt.rna.tf32.f32 %0, %1;" : "=r"(u) : "f"(x));
    return __uint_as_float(u);
}

__device__ __forceinline__ void mma_tf32(float c[4], uint32_t a0, uint32_t a1,
                                         uint32_t a2, uint32_t a3,
                                         uint32_t b0, uint32_t b1) {
    asm volatile(
        "mma.sync.aligned.m16n8k8.row.col.f32.tf32.tf32.f32 "
        "{%0,%1,%2,%3}, {%4,%5,%6,%7}, {%8,%9}, {%0,%1,%2,%3};"
        : "+f"(c[0]), "+f"(c[1]), "+f"(c[2]), "+f"(c[3])
        : "r"(a0), "r"(a1), "r"(a2), "r"(a3), "r"(b0), "r"(b1));
}

#define FBITS(x) __float_as_uint(x)

// ---------------- 1) adaLN embedding ----------------
__global__ void k_adaln(const float* __restrict__ t, const float* __restrict__ w,
                        const float* __restrict__ bb) {
    __shared__ float st[CSd];
    int b = blockIdx.y;
    for (int i = threadIdx.x; i < CSd; i += blockDim.x) {
        float x = t[b * CSd + i];
        st[i] = x / (1.0f + __expf(-x));
    }
    __syncthreads();
    int j = blockIdx.x * blockDim.x + threadIdx.x;   // < 2304
    float acc = bb[j];
    for (int i = 0; i < CSd; i++) acc += st[i] * w[i * 3 * CSd + j];
    g_emb[b * 3 * CSd + j] = acc;
}

// ---------------- 2) bs_norm = LN(bs)*(1+scale) + shift ----------------
__global__ void k_bsnorm(const float* __restrict__ bs) {
    int row = blockIdx.x;            // b*S + s
    int b = row >> 10;
    const float* x = bs + (size_t)row * CSd;
    int t = threadIdx.x, w = t >> 5, lane = t & 31;
    float s1 = 0.f, s2 = 0.f;
    for (int c = t; c < CSd; c += 256) { float v = x[c]; s1 += v; s2 += v * v; }
    s1 = warp_sum(s1); s2 = warp_sum(s2);
    __shared__ float r1[8], r2[8], smu, srs;
    if (lane == 0) { r1[w] = s1; r2[w] = s2; }
    __syncthreads();
    if (t == 0) {
        float a = 0.f, c2 = 0.f;
        for (int i = 0; i < 8; i++) { a += r1[i]; c2 += r2[i]; }
        float mu = a * (1.0f / CSd);
        float var = c2 * (1.0f / CSd) - mu * mu;
        smu = mu; srs = rsqrtf(var + EPSf);
    }
    __syncthreads();
    float mu = smu, rs = srs;
    const float* eb = g_emb + b * 3 * CSd;
    float* outr = g_bsnorm + (size_t)row * CSd;
    for (int c = t; c < CSd; c += 256) {
        float sc = eb[CSd + c];
        float sh = eb[c];
        outr[c] = (x[c] - mu) * rs * (1.0f + sc) + sh;
    }
}

// ---------------- 3) QKV GEMM (tf32 mma, 128x128 tiles, k-step 32, fused RMS) ----------------
// grid (6, 16, 3), block 256.
__global__ __launch_bounds__(256) void k_gemm_qkv(const float* __restrict__ wq,
                                                  const float* __restrict__ wk,
                                                  const float* __restrict__ wv,
                                                  const float* __restrict__ rqw,
                                                  const float* __restrict__ rkw) {
    __shared__ float As[128 * 36];    // stride 36 (== 4 mod 32)
    __shared__ float Ws[32 * 136];    // stride 136 (== 8 mod 32)
    int zsel = blockIdx.z;
    const float* W = (zsel == 0) ? wq : (zsel == 1) ? wk : wv;
    float* C = (zsel == 0) ? g_q : (zsel == 1) ? g_k : g_v;
    const float* A = g_bsnorm;
    int t = threadIdx.x, w = t >> 5, lane = t & 31;
    int lg = lane >> 2, lr = lane & 3;
    int m0 = blockIdx.y * 128, n0 = blockIdx.x * 128;
    int wm = (w & 3) * 32, wn = (w >> 2) * 64;
    float acc[2][8][4];
    #pragma unroll
    for (int mt = 0; mt < 2; mt++)
        #pragma unroll
        for (int nt = 0; nt < 8; nt++)
            #pragma unroll
            for (int j = 0; j < 4; j++) acc[mt][nt][j] = 0.f;

    for (int k0 = 0; k0 < CSd; k0 += 32) {
        __syncthreads();
        #pragma unroll
        for (int idx = t; idx < 1024; idx += 256) {
            int r = idx >> 3, c4 = (idx & 7) * 4;
            float4 v = *(const float4*)&A[(size_t)(m0 + r) * CSd + k0 + c4];
            float4 tv = {to_tf32(v.x), to_tf32(v.y), to_tf32(v.z), to_tf32(v.w)};
            *(float4*)&As[r * 36 + c4] = tv;
        }
        #pragma unroll
        for (int idx = t; idx < 1024; idx += 256) {
            int r = idx >> 5, c4 = (idx & 31) * 4;
            float4 v = *(const float4*)&W[(size_t)(k0 + r) * CSd + n0 + c4];
            float4 tv = {to_tf32(v.x), to_tf32(v.y), to_tf32(v.z), to_tf32(v.w)};
            *(float4*)&Ws[r * 136 + c4] = tv;
        }
        __syncthreads();
        #pragma unroll
        for (int kc = 0; kc < 4; kc++) {
            uint32_t a[2][4];
            #pragma unroll
            for (int mt = 0; mt < 2; mt++) {
                const float* ap = &As[(wm + mt * 16 + lg) * 36 + kc * 8 + lr];
                a[mt][0] = FBITS(ap[0]);       a[mt][1] = FBITS(ap[8 * 36]);
                a[mt][2] = FBITS(ap[4]);       a[mt][3] = FBITS(ap[8 * 36 + 4]);
            }
            #pragma unroll
            for (int nt = 0; nt < 8; nt++) {
                const float* wp = &Ws[(kc * 8 + lr) * 136 + wn + nt * 8 + lg];
                uint32_t b0 = FBITS(wp[0]), b1 = FBITS(wp[4 * 136]);
                mma_tf32(acc[0][nt], a[0][0], a[0][1], a[0][2], a[0][3], b0, b1);
                mma_tf32(acc[1][nt], a[1][0], a[1][1], a[1][2], a[1][3], b0, b1);
            }
        }
    }

    // fused RMS for q/k: each warp's 64-col tile = two whole 32-col heads
    if (zsel < 2) {
        const float* rw = (zsel == 0) ? rqw : rkw;
        float qsc = (zsel == 0) ? 0.17677669529663687f : 1.0f;   // 1/sqrt(32) into q
        #pragma unroll
        for (int mt = 0; mt < 2; mt++) {
            #pragma unroll
            for (int hg = 0; hg < 2; hg++) {
                float ss0 = 0.f, ss1 = 0.f;
                #pragma unroll
                for (int q = 0; q < 4; q++) {
                    int nt = hg * 4 + q;
                    ss0 += acc[mt][nt][0] * acc[mt][nt][0] + acc[mt][nt][1] * acc[mt][nt][1];
                    ss1 += acc[mt][nt][2] * acc[mt][nt][2] + acc[mt][nt][3] * acc[mt][nt][3];
                }
                ss0 += __shfl_xor_sync(0xffffffffu, ss0, 1);
                ss0 += __shfl_xor_sync(0xffffffffu, ss0, 2);
                ss1 += __shfl_xor_sync(0xffffffffu, ss1, 1);
                ss1 += __shfl_xor_sync(0xffffffffu, ss1, 2);
                float r0 = rsqrtf(ss0 * (1.0f / 32.0f) + EPSf) * qsc;
                float r1 = rsqrtf(ss1 * (1.0f / 32.0f) + EPSf) * qsc;
                #pragma unroll
                for (int q = 0; q < 4; q++) {
                    int nt = hg * 4 + q;
                    int d = q * 8 + 2 * lr;
                    float w0 = rw[d], w1 = rw[d + 1];
                    acc[mt][nt][0] *= r0 * w0; acc[mt][nt][1] *= r0 * w1;
                    acc[mt][nt][2] *= r1 * w0; acc[mt][nt][3] *= r1 * w1;
                }
            }
        }
    }

    #pragma unroll
    for (int mt = 0; mt < 2; mt++)
        #pragma unroll
        for (int nt = 0; nt < 8; nt++) {
            int row = m0 + wm + mt * 16 + lg;
            int col = n0 + wn + nt * 8 + 2 * lr;
            float2 v0 = {acc[mt][nt][0], acc[mt][nt][1]};
            float2 v1 = {acc[mt][nt][2], acc[mt][nt][3]};
            *(float2*)&C[(size_t)row * CSd + col] = v0;
            *(float2*)&C[(size_t)(row + 8) * CSd + col] = v1;
        }
}

// ---------------- 5) bias via tf32 mma: [256x128] @ [128x24] per CTA ----------------
#define BIAS_SM_FLOATS (256 * 68 + 128 * 40 + 256 * 3 + 48)
__global__ __launch_bounds__(256, 2) void k_bias(const float* __restrict__ z,
                                                 const int* __restrict__ z_mask,
                                                 const float* __restrict__ lnw,
                                                 const float* __restrict__ lnb,
                                                 const float* __restrict__ wz) {
    extern __shared__ float sb[];
    float* zs  = sb;                 // [256][68]   stride 68 (==4 mod 32)
    float* wzs = zs + 256 * 68;      // [128][40]   stride 40 (==8 mod 32)
    float* mus = wzs + 128 * 40;     // [256]
    float* rsg = mus + 256;          // [256]
    float* mbs = rsg + 256;          // [256]
    float* Ah  = mbs + 256;          // [24]
    float* Bh  = Ah + 24;            // [24]
    int t = threadIdx.x, w = t >> 5, lane = t & 31;
    int lg = lane >> 2, lr = lane & 3;
    int wr = w * 32;
    size_t pair0 = (size_t)blockIdx.x * 256;
    int i_row = (int)(pair0 >> 10);
    int j0 = (int)(pair0 & 1023);

    for (int idx = t; idx < 128 * 24; idx += 256) {
        int k = idx / 24, hh = idx - k * 24;
        wzs[k * 40 + hh] = to_tf32(lnw[k] * wz[idx]);
    }
    if (t < 24) {
        float a = 0.f, bsum = 0.f;
        for (int c = 0; c < 128; c++) {
            float wv = wz[c * 24 + t];
            a += lnw[c] * wv; bsum += lnb[c] * wv;
        }
        Ah[t] = a; Bh[t] = bsum;
    }
    mbs[t] = (z_mask[i_row * SS + j0 + t] != 0) ? 0.0f : NEG_INF;

    float acc[2][3][4];
    #pragma unroll
    for (int mt = 0; mt < 2; mt++)
        #pragma unroll
        for (int nt = 0; nt < 3; nt++)
            #pragma unroll
            for (int j = 0; j < 4; j++) acc[mt][nt][j] = 0.f;

    float s1 = 0.f, s2 = 0.f;
    #pragma unroll
    for (int half = 0; half < 2; half++) {
        __syncthreads();
        #pragma unroll
        for (int idx = t; idx < 4096; idx += 256) {   // 256 pairs x 16 float4
            int p = idx >> 4, c4 = (idx & 15) * 4;
            float4 v = *(const float4*)&z[(pair0 + p) * 128 + half * 64 + c4];
            float4 tv = {to_tf32(v.x), to_tf32(v.y), to_tf32(v.z), to_tf32(v.w)};
            *(float4*)&zs[p * 68 + c4] = tv;
        }
        __syncthreads();
        {   // per-pair stats (thread t owns pair t)
            const float* zr = &zs[t * 68];
            for (int c = 0; c < 64; c++) { float v = zr[c]; s1 += v; s2 += v * v; }
        }
        if (half == 1) {
            float mu = s1 * (1.0f / 128.0f);
            float var = s2 * (1.0f / 128.0f) - mu * mu;
            mus[t] = mu; rsg[t] = rsqrtf(var + EPSf);
        }
        #pragma unroll
        for (int kc = 0; kc < 8; kc++) {
            uint32_t a[2][4];
            #pragma unroll
            for (int mt = 0; mt < 2; mt++) {
                const float* ap = &zs[(wr + mt * 16 + lg) * 68 + kc * 8 + lr];
                a[mt][0] = FBITS(ap[0]);     a[mt][1] = FBITS(ap[8 * 68]);
                a[mt][2] = FBITS(ap[4]);     a[mt][3] = FBITS(ap[8 * 68 + 4]);
            }
            #pragma unroll
            for (int nt = 0; nt < 3; nt++) {
                const float* wp = &wzs[(half * 64 + kc * 8 + lr) * 40 + nt * 8 + lg];
                uint32_t b0 = FBITS(wp[0]), b1 = FBITS(wp[4 * 40]);
                mma_tf32(acc[0][nt], a[0][0], a[0][1], a[0][2], a[0][3], b0, b1);
                mma_tf32(acc[1][nt], a[1][0], a[1][1], a[1][2], a[1][3], b0, b1);
            }
        }
    }
    __syncthreads();   // mus/rsg visible to all
    #pragma unroll
    for (int mt = 0; mt < 2; mt++)
        #pragma unroll
        for (int nt = 0; nt < 3; nt++) {
            int p0 = wr + mt * 16 + lg;
            int hh = nt * 8 + 2 * lr;
            #pragma unroll
            for (int half = 0; half < 2; half++) {
                int p = p0 + half * 8;
                float mu = mus[p], rs = rsg[p], mb = mbs[p];
                float v0 = (acc[mt][nt][2 * half + 0] - mu * Ah[hh]) * rs + Bh[hh] + mb;
                float v1 = (acc[mt][nt][2 * half + 1] - mu * Ah[hh + 1]) * rs + Bh[hh + 1] + mb;
                size_t base = (size_t)i_row * SS + j0 + p;
                g_bias[(size_t)hh * SS * SS + base] = v0;
                g_bias[(size_t)(hh + 1) * SS * SS + base] = v1;
            }
        }
}

// ---------------- 6) flash attention, tf32 mma, 128 q-rows/CTA ----------------
// grid (2, 24, 8): x=b (fastest, bias L2 reuse), y=h (beta L2 reuse), z=qt
#define ATTN_SM_FLOATS (128 * 36 + 64 * 36 + 64 * 40 + 128 * 68)
__global__ __launch_bounds__(256, 2) void k_attn(const float* __restrict__ beta) {
    extern __shared__ float sa[];
    float* Qs = sa;                   // [128][36]  (==4 mod 32)
    float* Ks = Qs + 128 * 36;        // [64][36]
    float* Vs = Ks + 64 * 36;         // [64][40]   (==8 mod 32)
    float* Ps = Vs + 64 * 40;         // [128][68]  P staging (warp-private rows)
    int b = blockIdx.x, h = blockIdx.y, qt = blockIdx.z;
    int t = threadIdx.x, w = t >> 5, lane = t & 31;
    int lg = lane >> 2, lr = lane & 3;
    int wr = w * 16;

    const float* qg = g_q + ((size_t)(b * SS + qt * 128)) * CSd + h * Dd;
    #pragma unroll
    for (int idx = t; idx < 128 * 8; idx += 256) {
        int r = idx >> 3, c4 = (idx & 7) * 4;
        float4 v = *(const float4*)&qg[(size_t)r * CSd + c4];
        float4 tv = {to_tf32(v.x), to_tf32(v.y), to_tf32(v.z), to_tf32(v.w)};
        *(float4*)&Qs[r * 36 + c4] = tv;
    }

    float O[4][4];
    #pragma unroll
    for (int dn = 0; dn < 4; dn++)
        #pragma unroll
        for (int j = 0; j < 4; j++) O[dn][j] = 0.f;
    float m0 = -1e30f, m1 = -1e30f, l0 = 0.f, l1 = 0.f;

    const float* bias_b = g_bias + ((size_t)h << 20) + (size_t)(qt * 128) * SS;
    const float* beta_b = beta + ((size_t)b << 20) + (size_t)(qt * 128) * SS;
    const float* kg = g_k + (size_t)(b * SS) * CSd + h * Dd;
    const float* vg = g_v + (size_t)(b * SS) * CSd + h * Dd;

    for (int kt = 0; kt < 16; kt++) {
        __syncthreads();
        #pragma unroll
        for (int idx = t; idx < 64 * 8; idx += 256) {
            int r = idx >> 3, c4 = (idx & 7) * 4;
            float4 kv = *(const float4*)&kg[(size_t)(kt * 64 + r) * CSd + c4];
            float4 vv = *(const float4*)&vg[(size_t)(kt * 64 + r) * CSd + c4];
            float4 tk = {to_tf32(kv.x), to_tf32(kv.y), to_tf32(kv.z), to_tf32(kv.w)};
            float4 tv = {to_tf32(vv.x), to_tf32(vv.y), to_tf32(vv.z), to_tf32(vv.w)};
            *(float4*)&Ks[r * 36 + c4] = tk;
            *(float4*)&Vs[r * 40 + c4] = tv;
        }
        __syncthreads();

        // ---- S = Q @ K^T ----
        uint32_t qa[4][4];
        #pragma unroll
        for (int kc = 0; kc < 4; kc++) {
            const float* qp = &Qs[(wr + lg) * 36 + kc * 8 + lr];
            qa[kc][0] = FBITS(qp[0]);      qa[kc][1] = FBITS(qp[8 * 36]);
            qa[kc][2] = FBITS(qp[4]);      qa[kc][3] = FBITS(qp[8 * 36 + 4]);
        }
        float S[8][4];
        #pragma unroll
        for (int nt = 0; nt < 8; nt++) {
            S[nt][0] = S[nt][1] = S[nt][2] = S[nt][3] = 0.f;
            #pragma unroll
            for (int kc = 0; kc < 4; kc++) {
                const float* kp = &Ks[(nt * 8 + lg) * 36 + kc * 8 + lr];
                uint32_t b0 = FBITS(kp[0]), b1 = FBITS(kp[4]);
                mma_tf32(S[nt], qa[kc][0], qa[kc][1], qa[kc][2], qa[kc][3], b0, b1);
            }
        }
        // ---- direct bias+beta add at fragment coords (L2-hot) ----
        {
            const float* bp0 = bias_b + (size_t)(wr + lg) * SS + kt * 64 + 2 * lr;
            const float* tp0 = beta_b + (size_t)(wr + lg) * SS + kt * 64 + 2 * lr;
            #pragma unroll
            for (int nt = 0; nt < 8; nt++) {
                float2 x0 = *(const float2*)(bp0 + nt * 8);
                float2 y0 = *(const float2*)(tp0 + nt * 8);
                S[nt][0] += x0.x + y0.x;  S[nt][1] += x0.y + y0.y;
                float2 x1 = *(const float2*)(bp0 + 8 * SS + nt * 8);
                float2 y1 = *(const float2*)(tp0 + 8 * SS + nt * 8);
                S[nt][2] += x1.x + y1.x;  S[nt][3] += x1.y + y1.y;
            }
        }
        // ---- online softmax (rows warp-local, stats across quad) ----
        float mp0 = -1e30f, mp1 = -1e30f;
        #pragma unroll
        for (int nt = 0; nt < 8; nt++) {
            mp0 = fmaxf(mp0, fmaxf(S[nt][0], S[nt][1]));
            mp1 = fmaxf(mp1, fmaxf(S[nt][2], S[nt][3]));
        }
        mp0 = fmaxf(mp0, __shfl_xor_sync(0xffffffffu, mp0, 1));
        mp0 = fmaxf(mp0, __shfl_xor_sync(0xffffffffu, mp0, 2));
        mp1 = fmaxf(mp1, __shfl_xor_sync(0xffffffffu, mp1, 1));
        mp1 = fmaxf(mp1, __shfl_xor_sync(0xffffffffu, mp1, 2));
        float nm0 = fmaxf(m0, mp0), nm1 = fmaxf(m1, mp1);
        float c0 = __expf(m0 - nm0), c1 = __expf(m1 - nm1);
        m0 = nm0; m1 = nm1;
        float s0 = 0.f, s1 = 0.f;
        #pragma unroll
        for (int nt = 0; nt < 8; nt++) {
            S[nt][0] = __expf(S[nt][0] - nm0);
            S[nt][1] = __expf(S[nt][1] - nm0);
            S[nt][2] = __expf(S[nt][2] - nm1);
            S[nt][3] = __expf(S[nt][3] - nm1);
            s0 += S[nt][0] + S[nt][1];
            s1 += S[nt][2] + S[nt][3];
            float* pb = &Ps[(wr + lg) * 68 + nt * 8 + 2 * lr];
            pb[0] = to_tf32(S[nt][0]);          pb[1] = to_tf32(S[nt][1]);
            pb[8 * 68] = to_tf32(S[nt][2]);     pb[8 * 68 + 1] = to_tf32(S[nt][3]);
        }
        s0 += __shfl_xor_sync(0xffffffffu, s0, 1);
        s0 += __shfl_xor_sync(0xffffffffu, s0, 2);
        s1 += __shfl_xor_sync(0xffffffffu, s1, 1);
        s1 += __shfl_xor_sync(0xffffffffu, s1, 2);
        l0 = l0 * c0 + s0;
        l1 = l1 * c1 + s1;
        #pragma unroll
        for (int dn = 0; dn < 4; dn++) {
            O[dn][0] *= c0; O[dn][1] *= c0; O[dn][2] *= c1; O[dn][3] *= c1;
        }
        __syncwarp();
        // ---- O += P @ V ----
        #pragma unroll
        for (int kc = 0; kc < 8; kc++) {
            const float* pp = &Ps[(wr + lg) * 68 + kc * 8 + lr];
            uint32_t a0 = FBITS(pp[0]), a1 = FBITS(pp[8 * 68]);
            uint32_t a2 = FBITS(pp[4]), a3 = FBITS(pp[8 * 68 + 4]);
            #pragma unroll
            for (int dn = 0; dn < 4; dn++) {
                const float* vp = &Vs[(kc * 8 + lr) * 40 + dn * 8 + lg];
                uint32_t b0 = FBITS(vp[0]), b1 = FBITS(vp[4 * 40]);
                mma_tf32(O[dn], a0, a1, a2, a3, b0, b1);
            }
        }
        __syncwarp();
    }
    // epilogue
    float inv0 = 1.0f / l0, inv1 = 1.0f / l1;
    float* og = g_attno + ((size_t)(b * SS + qt * 128)) * CSd + h * Dd;
    #pragma unroll
    for (int dn = 0; dn < 4; dn++) {
        int col = dn * 8 + 2 * lr;
        int r0 = wr + lg;
        float2 v0 = {O[dn][0] * inv0, O[dn][1] * inv0};
        float2 v1 = {O[dn][2] * inv1, O[dn][3] * inv1};
        *(float2*)&og[(size_t)r0 * CSd + col] = v0;
        *(float2*)&og[(size_t)(r0 + 8) * CSd + col] = v1;
    }
}

// ---------------- 7) out projection + bias + gate (tf32 mma) ----------------
// grid (6, 16), block 256
__global__ __launch_bounds__(256) void k_gemm_out(const float* __restrict__ wo,
                                                  const float* __restrict__ bo,
                                                  float* __restrict__ out) {
    __shared__ float As[128 * 36];
    __shared__ float Ws[32 * 136];
    const float* A = g_attno;
    int t = threadIdx.x, w = t >> 5, lane = t & 31;
    int lg = lane >> 2, lr = lane & 3;
    int m0 = blockIdx.y * 128, n0 = blockIdx.x * 128;
    int wm = (w & 3) * 32, wn = (w >> 2) * 64;
    float acc[2][8][4];
    #pragma unroll
    for (int mt = 0; mt < 2; mt++)
        #pragma unroll
        for (int nt = 0; nt < 8; nt++)
            #pragma unroll
            for (int j = 0; j < 4; j++) acc[mt][nt][j] = 0.f;

    for (int k0 = 0; k0 < CSd; k0 += 32) {
        __syncthreads();
        #pragma unroll
        for (int idx = t; idx < 1024; idx += 256) {
            int r = idx >> 3, c4 = (idx & 7) * 4;
            float4 v = *(const float4*)&A[(size_t)(m0 + r) * CSd + k0 + c4];
            float4 tv = {to_tf32(v.x), to_tf32(v.y), to_tf32(v.z), to_tf32(v.w)};
            *(float4*)&As[r * 36 + c4] = tv;
        }
        #pragma unroll
        for (int idx = t; idx < 1024; idx += 256) {
            int r = idx >> 5, c4 = (idx & 31) * 4;
            float4 v = *(const float4*)&wo[(size_t)(k0 + r) * CSd + n0 + c4];
            float4 tv = {to_tf32(v.x), to_tf32(v.y), to_tf32(v.z), to_tf32(v.w)};
            *(float4*)&Ws[r * 136 + c4] = tv;
        }
        __syncthreads();
        #pragma unroll
        for (int kc = 0; kc < 4; kc++) {
            uint32_t a[2][4];
            #pragma unroll
            for (int mt = 0; mt < 2; mt++) {
                const float* ap = &As[(wm + mt * 16 + lg) * 36 + kc * 8 + lr];
                a[mt][0] = FBITS(ap[0]);       a[mt][1] = FBITS(ap[8 * 36]);
                a[mt][2] = FBITS(ap[4]);       a[mt][3] = FBITS(ap[8 * 36 + 4]);
            }
            #pragma unroll
            for (int nt = 0; nt < 8; nt++) {
                const float* wp = &Ws[(kc * 8 + lr) * 136 + wn + nt * 8 + lg];
                uint32_t b0 = FBITS(wp[0]), b1 = FBITS(wp[4 * 136]);
                mma_tf32(acc[0][nt], a[0][0], a[0][1], a[0][2], a[0][3], b0, b1);
                mma_tf32(acc[1][nt], a[1][0], a[1][1], a[1][2], a[1][3], b0, b1);
            }
        }
    }
    #pragma unroll
    for (int mt = 0; mt < 2; mt++)
        #pragma unroll
        for (int nt = 0; nt < 8; nt++) {
            int row = m0 + wm + mt * 16 + lg;
            int col = n0 + wn + nt * 8 + 2 * lr;
            int bidx = row >> 10;
            const float* gate = g_emb + bidx * 3 * CSd + 2 * CSd;
            float gb0 = gate[col], gb1 = gate[col + 1];
            float bb0 = bo[col], bb1 = bo[col + 1];
            float2 v0 = {(acc[mt][nt][0] + bb0) * gb0, (acc[mt][nt][1] + bb1) * gb1};
            float2 v1 = {(acc[mt][nt][2] + bb0) * gb0, (acc[mt][nt][3] + bb1) * gb1};
            *(float2*)&out[(size_t)row * CSd + col] = v0;
            *(float2*)&out[(size_t)(row + 8) * CSd + col] = v1;
        }
}

// ---------------- launch (fork k_bias onto a side stream, join before attn) ----------------
extern "C" void kernel_launch(void* const* d_in, const int* in_sizes, int n_in,
                              void* d_out, int out_size) {
    const float* bs      = (const float*)d_in[0];
    const float* z       = (const float*)d_in[1];
    const float* t       = (const float*)d_in[2];
    const float* beta    = (const float*)d_in[3];
    const int*   z_mask  = (const int*)d_in[4];
    const float* w_adaln = (const float*)d_in[5];
    const float* b_adaln = (const float*)d_in[6];
    const float* ln_z_w  = (const float*)d_in[7];
    const float* ln_z_b  = (const float*)d_in[8];
    const float* w_q     = (const float*)d_in[9];
    const float* w_k     = (const float*)d_in[10];
    const float* w_v     = (const float*)d_in[11];
    const float* w_z     = (const float*)d_in[12];
    const float* rms_q_w = (const float*)d_in[13];
    const float* rms_k_w = (const float*)d_in[14];
    const float* w_o     = (const float*)d_in[15];
    const float* b_o     = (const float*)d_in[16];
    float* out = (float*)d_out;

    static cudaStream_t s_bias = nullptr;
    static cudaEvent_t ev_fork = nullptr, ev_join = nullptr;
    if (s_bias == nullptr) {
        (void)cudaStreamCreateWithFlags(&s_bias, cudaStreamNonBlocking);
        (void)cudaEventCreateWithFlags(&ev_fork, cudaEventDisableTiming);
        (void)cudaEventCreateWithFlags(&ev_join, cudaEventDisableTiming);
        (void)cudaFuncSetAttribute(k_bias, cudaFuncAttributeMaxDynamicSharedMemorySize,
                                   BIAS_SM_FLOATS * (int)sizeof(float));
        (void)cudaFuncSetAttribute(k_attn, cudaFuncAttributeMaxDynamicSharedMemorySize,
                                   ATTN_SM_FLOATS * (int)sizeof(float));
    }

    // fork: bias path is independent of the bs/t path
    (void)cudaEventRecord(ev_fork, 0);
    (void)cudaStreamWaitEvent(s_bias, ev_fork, 0);
    k_bias<<<4096, 256, BIAS_SM_FLOATS * (int)sizeof(float), s_bias>>>(
        z, z_mask, ln_z_w, ln_z_b, w_z);
    (void)cudaEventRecord(ev_join, s_bias);

    // main chain
    k_adaln<<<dim3(18, 2), 128>>>(t, w_adaln, b_adaln);
    k_bsnorm<<<BB * SS, 256>>>(bs);
    k_gemm_qkv<<<dim3(6, 16, 3), 256>>>(w_q, w_k, w_v, rms_q_w, rms_k_w);

    // join, then attention + out-proj
    (void)cudaStreamWaitEvent(0, ev_join, 0);
    k_attn<<<dim3(2, 24, 8), 256, ATTN_SM_FLOATS * (int)sizeof(float)>>>(beta);
    k_gemm_out<<<dim3(6, 16), 256>>>(w_o, b_o, out);
}

// round 8
// speedup vs baseline: 3.2961x; 1.0763x over previous
#include <cuda_runtime.h>
#include <math.h>
#include <stdint.h>

#define BB   2
#define SS   1024
#define CSd  768
#define CZd  128
#define Dd   32
#define Hd   24
#define EPSf 1e-5f
#define NEG_INF (-1e9f)

// ---------------- scratch (static device globals; no allocation) ----------------
__device__ float g_emb[BB * 3 * CSd];                 // adaLN shift|scale|gate
__device__ float g_bsnorm[BB * SS * CSd];             // modulated LN(bs)
__device__ float g_q[BB * SS * CSd];                  // [b][s][h*D+d] (rms+1/sqrtD folded)
__device__ float g_k[BB * SS * CSd];                  // (rms folded)
__device__ float g_v[BB * SS * CSd];
__device__ float g_attno[BB * SS * CSd];              // attention output pre-proj
__device__ float g_bias[(size_t)Hd * SS * SS];        // [h][i][j]  (100MB)

__inline__ __device__ float warp_sum(float v) {
    #pragma unroll
    for (int o = 16; o > 0; o >>= 1) v += __shfl_xor_sync(0xffffffffu, v, o);
    return v;
}

__device__ __forceinline__ float to_tf32(float x) {
    uint32_t u;
    asm("cvt.rna.tf32.f32 %0, %1;" : "=r"(u) : "f"(x));
    return __uint_as_float(u);
}

__device__ __forceinline__ void mma_tf32(float c[4], uint32_t a0, uint32_t a1,
                                         uint32_t a2, uint32_t a3,
                                         uint32_t b0, uint32_t b1) {
    asm volatile(
        "mma.sync.aligned.m16n8k8.row.col.f32.tf32.tf32.f32 "
        "{%0,%1,%2,%3}, {%4,%5,%6,%7}, {%8,%9}, {%0,%1,%2,%3};"
        : "+f"(c[0]), "+f"(c[1]), "+f"(c[2]), "+f"(c[3])
        : "r"(a0), "r"(a1), "r"(a2), "r"(a3), "r"(b0), "r"(b1));
}

#define FBITS(x) __float_as_uint(x)

// ---------------- 1) adaLN embedding ----------------
__global__ void k_adaln(const float* __restrict__ t, const float* __restrict__ w,
                        const float* __restrict__ bb) {
    __shared__ float st[CSd];
    int b = blockIdx.y;
    for (int i = threadIdx.x; i < CSd; i += blockDim.x) {
        float x = t[b * CSd + i];
        st[i] = x / (1.0f + __expf(-x));
    }
    __syncthreads();
    int j = blockIdx.x * blockDim.x + threadIdx.x;   // < 2304
    float acc = bb[j];
    for (int i = 0; i < CSd; i++) acc += st[i] * w[i * 3 * CSd + j];
    g_emb[b * 3 * CSd + j] = acc;
}

// ---------------- 2) bs_norm = LN(bs)*(1+scale) + shift ----------------
__global__ void k_bsnorm(const float* __restrict__ bs) {
    int row = blockIdx.x;            // b*S + s
    int b = row >> 10;
    const float* x = bs + (size_t)row * CSd;
    int t = threadIdx.x, w = t >> 5, lane = t & 31;
    float s1 = 0.f, s2 = 0.f;
    for (int c = t; c < CSd; c += 256) { float v = x[c]; s1 += v; s2 += v * v; }
    s1 = warp_sum(s1); s2 = warp_sum(s2);
    __shared__ float r1[8], r2[8], smu, srs;
    if (lane == 0) { r1[w] = s1; r2[w] = s2; }
    __syncthreads();
    if (t == 0) {
        float a = 0.f, c2 = 0.f;
        for (int i = 0; i < 8; i++) { a += r1[i]; c2 += r2[i]; }
        float mu = a * (1.0f / CSd);
        float var = c2 * (1.0f / CSd) - mu * mu;
        smu = mu; srs = rsqrtf(var + EPSf);
    }
    __syncthreads();
    float mu = smu, rs = srs;
    const float* eb = g_emb + b * 3 * CSd;
    float* outr = g_bsnorm + (size_t)row * CSd;
    for (int c = t; c < CSd; c += 256) {
        float sc = eb[CSd + c];
        float sh = eb[c];
        outr[c] = (x[c] - mu) * rs * (1.0f + sc) + sh;
    }
}

// ---------------- 3) QKV GEMM (tf32 mma, 128x128 tiles, k-step 32, fused RMS) ----------------
// grid (6, 16, 3), block 256.
__global__ __launch_bounds__(256) void k_gemm_qkv(const float* __restrict__ wq,
                                                  const float* __restrict__ wk,
                                                  const float* __restrict__ wv,
                                                  const float* __restrict__ rqw,
                                                  const float* __restrict__ rkw) {
    __shared__ float As[128 * 36];    // stride 36 (== 4 mod 32)
    __shared__ float Ws[32 * 136];    // stride 136 (== 8 mod 32)
    int zsel = blockIdx.z;
    const float* W = (zsel == 0) ? wq : (zsel == 1) ? wk : wv;
    float* C = (zsel == 0) ? g_q : (zsel == 1) ? g_k : g_v;
    const float* A = g_bsnorm;
    int t = threadIdx.x, w = t >> 5, lane = t & 31;
    int lg = lane >> 2, lr = lane & 3;
    int m0 = blockIdx.y * 128, n0 = blockIdx.x * 128;
    int wm = (w & 3) * 32, wn = (w >> 2) * 64;
    float acc[2][8][4];
    #pragma unroll
    for (int mt = 0; mt < 2; mt++)
        #pragma unroll
        for (int nt = 0; nt < 8; nt++)
            #pragma unroll
            for (int j = 0; j < 4; j++) acc[mt][nt][j] = 0.f;

    for (int k0 = 0; k0 < CSd; k0 += 32) {
        __syncthreads();
        #pragma unroll
        for (int idx = t; idx < 1024; idx += 256) {
            int r = idx >> 3, c4 = (idx & 7) * 4;
            float4 v = *(const float4*)&A[(size_t)(m0 + r) * CSd + k0 + c4];
            float4 tv = {to_tf32(v.x), to_tf32(v.y), to_tf32(v.z), to_tf32(v.w)};
            *(float4*)&As[r * 36 + c4] = tv;
        }
        #pragma unroll
        for (int idx = t; idx < 1024; idx += 256) {
            int r = idx >> 5, c4 = (idx & 31) * 4;
            float4 v = *(const float4*)&W[(size_t)(k0 + r) * CSd + n0 + c4];
            float4 tv = {to_tf32(v.x), to_tf32(v.y), to_tf32(v.z), to_tf32(v.w)};
            *(float4*)&Ws[r * 136 + c4] = tv;
        }
        __syncthreads();
        #pragma unroll
        for (int kc = 0; kc < 4; kc++) {
            uint32_t a[2][4];
            #pragma unroll
            for (int mt = 0; mt < 2; mt++) {
                const float* ap = &As[(wm + mt * 16 + lg) * 36 + kc * 8 + lr];
                a[mt][0] = FBITS(ap[0]);       a[mt][1] = FBITS(ap[8 * 36]);
                a[mt][2] = FBITS(ap[4]);       a[mt][3] = FBITS(ap[8 * 36 + 4]);
            }
            #pragma unroll
            for (int nt = 0; nt < 8; nt++) {
                const float* wp = &Ws[(kc * 8 + lr) * 136 + wn + nt * 8 + lg];
                uint32_t b0 = FBITS(wp[0]), b1 = FBITS(wp[4 * 136]);
                mma_tf32(acc[0][nt], a[0][0], a[0][1], a[0][2], a[0][3], b0, b1);
                mma_tf32(acc[1][nt], a[1][0], a[1][1], a[1][2], a[1][3], b0, b1);
            }
        }
    }

    // fused RMS for q/k: each warp's 64-col tile = two whole 32-col heads
    if (zsel < 2) {
        const float* rw = (zsel == 0) ? rqw : rkw;
        float qsc = (zsel == 0) ? 0.17677669529663687f : 1.0f;   // 1/sqrt(32) into q
        #pragma unroll
        for (int mt = 0; mt < 2; mt++) {
            #pragma unroll
            for (int hg = 0; hg < 2; hg++) {
                float ss0 = 0.f, ss1 = 0.f;
                #pragma unroll
                for (int q = 0; q < 4; q++) {
                    int nt = hg * 4 + q;
                    ss0 += acc[mt][nt][0] * acc[mt][nt][0] + acc[mt][nt][1] * acc[mt][nt][1];
                    ss1 += acc[mt][nt][2] * acc[mt][nt][2] + acc[mt][nt][3] * acc[mt][nt][3];
                }
                ss0 += __shfl_xor_sync(0xffffffffu, ss0, 1);
                ss0 += __shfl_xor_sync(0xffffffffu, ss0, 2);
                ss1 += __shfl_xor_sync(0xffffffffu, ss1, 1);
                ss1 += __shfl_xor_sync(0xffffffffu, ss1, 2);
                float r0 = rsqrtf(ss0 * (1.0f / 32.0f) + EPSf) * qsc;
                float r1 = rsqrtf(ss1 * (1.0f / 32.0f) + EPSf) * qsc;
                #pragma unroll
                for (int q = 0; q < 4; q++) {
                    int nt = hg * 4 + q;
                    int d = q * 8 + 2 * lr;
                    float w0 = rw[d], w1 = rw[d + 1];
                    acc[mt][nt][0] *= r0 * w0; acc[mt][nt][1] *= r0 * w1;
                    acc[mt][nt][2] *= r1 * w0; acc[mt][nt][3] *= r1 * w1;
                }
            }
        }
    }

    #pragma unroll
    for (int mt = 0; mt < 2; mt++)
        #pragma unroll
        for (int nt = 0; nt < 8; nt++) {
            int row = m0 + wm + mt * 16 + lg;
            int col = n0 + wn + nt * 8 + 2 * lr;
            float2 v0 = {acc[mt][nt][0], acc[mt][nt][1]};
            float2 v1 = {acc[mt][nt][2], acc[mt][nt][3]};
            *(float2*)&C[(size_t)row * CSd + col] = v0;
            *(float2*)&C[(size_t)(row + 8) * CSd + col] = v1;
        }
}

// ---------------- 5) bias via tf32 mma: [256x128] @ [128x24] per CTA ----------------
#define BIAS_SM_FLOATS (256 * 68 + 128 * 40 + 256 * 3 + 48)
__global__ __launch_bounds__(256, 2) void k_bias(const float* __restrict__ z,
                                                 const int* __restrict__ z_mask,
                                                 const float* __restrict__ lnw,
                                                 const float* __restrict__ lnb,
                                                 const float* __restrict__ wz) {
    extern __shared__ float sb[];
    float* zs  = sb;                 // [256][68]   stride 68 (==4 mod 32)
    float* wzs = zs + 256 * 68;      // [128][40]   stride 40 (==8 mod 32)
    float* mus = wzs + 128 * 40;     // [256]
    float* rsg = mus + 256;          // [256]
    float* mbs = rsg + 256;          // [256]
    float* Ah  = mbs + 256;          // [24]
    float* Bh  = Ah + 24;            // [24]
    int t = threadIdx.x, w = t >> 5, lane = t & 31;
    int lg = lane >> 2, lr = lane & 3;
    int wr = w * 32;
    size_t pair0 = (size_t)blockIdx.x * 256;
    int i_row = (int)(pair0 >> 10);
    int j0 = (int)(pair0 & 1023);

    for (int idx = t; idx < 128 * 24; idx += 256) {
        int k = idx / 24, hh = idx - k * 24;
        wzs[k * 40 + hh] = to_tf32(lnw[k] * wz[idx]);
    }
    if (t < 24) {
        float a = 0.f, bsum = 0.f;
        for (int c = 0; c < 128; c++) {
            float wv = wz[c * 24 + t];
            a += lnw[c] * wv; bsum += lnb[c] * wv;
        }
        Ah[t] = a; Bh[t] = bsum;
    }
    mbs[t] = (z_mask[i_row * SS + j0 + t] != 0) ? 0.0f : NEG_INF;

    float acc[2][3][4];
    #pragma unroll
    for (int mt = 0; mt < 2; mt++)
        #pragma unroll
        for (int nt = 0; nt < 3; nt++)
            #pragma unroll
            for (int j = 0; j < 4; j++) acc[mt][nt][j] = 0.f;

    float s1 = 0.f, s2 = 0.f;
    #pragma unroll
    for (int half = 0; half < 2; half++) {
        __syncthreads();
        #pragma unroll
        for (int idx = t; idx < 4096; idx += 256) {   // 256 pairs x 16 float4
            int p = idx >> 4, c4 = (idx & 15) * 4;
            float4 v = *(const float4*)&z[(pair0 + p) * 128 + half * 64 + c4];
            float4 tv = {to_tf32(v.x), to_tf32(v.y), to_tf32(v.z), to_tf32(v.w)};
            *(float4*)&zs[p * 68 + c4] = tv;
        }
        __syncthreads();
        {   // per-pair stats (thread t owns pair t)
            const float* zr = &zs[t * 68];
            for (int c = 0; c < 64; c++) { float v = zr[c]; s1 += v; s2 += v * v; }
        }
        if (half == 1) {
            float mu = s1 * (1.0f / 128.0f);
            float var = s2 * (1.0f / 128.0f) - mu * mu;
            mus[t] = mu; rsg[t] = rsqrtf(var + EPSf);
        }
        #pragma unroll
        for (int kc = 0; kc < 8; kc++) {
            uint32_t a[2][4];
            #pragma unroll
            for (int mt = 0; mt < 2; mt++) {
                const float* ap = &zs[(wr + mt * 16 + lg) * 68 + kc * 8 + lr];
                a[mt][0] = FBITS(ap[0]);     a[mt][1] = FBITS(ap[8 * 68]);
                a[mt][2] = FBITS(ap[4]);     a[mt][3] = FBITS(ap[8 * 68 + 4]);
            }
            #pragma unroll
            for (int nt = 0; nt < 3; nt++) {
                const float* wp = &wzs[(half * 64 + kc * 8 + lr) * 40 + nt * 8 + lg];
                uint32_t b0 = FBITS(wp[0]), b1 = FBITS(wp[4 * 40]);
                mma_tf32(acc[0][nt], a[0][0], a[0][1], a[0][2], a[0][3], b0, b1);
                mma_tf32(acc[1][nt], a[1][0], a[1][1], a[1][2], a[1][3], b0, b1);
            }
        }
    }
    __syncthreads();   // mus/rsg visible to all
    #pragma unroll
    for (int mt = 0; mt < 2; mt++)
        #pragma unroll
        for (int nt = 0; nt < 3; nt++) {
            int p0 = wr + mt * 16 + lg;
            int hh = nt * 8 + 2 * lr;
            #pragma unroll
            for (int half = 0; half < 2; half++) {
                int p = p0 + half * 8;
                float mu = mus[p], rs = rsg[p], mb = mbs[p];
                float v0 = (acc[mt][nt][2 * half + 0] - mu * Ah[hh]) * rs + Bh[hh] + mb;
                float v1 = (acc[mt][nt][2 * half + 1] - mu * Ah[hh + 1]) * rs + Bh[hh + 1] + mb;
                size_t base = (size_t)i_row * SS + j0 + p;
                g_bias[(size_t)hh * SS * SS + base] = v0;
                g_bias[(size_t)(hh + 1) * SS * SS + base] = v1;
            }
        }
}

// ---------------- 6) flash attention, tf32 mma, no-max single-pass softmax ----------------
// grid (2, 24, 8): x=b (fastest, bias L2 reuse), y=h (beta L2 reuse), z=qt
// Scores are bounded (|q|=1, |k|=sqrt(32), |bias|<~3, |beta|<~1 -> s < ~12), masked = -1e9.
// So: clamp at -80, exp directly, normalize once at the end. Identical math, no m/corr state.
#define ATTN_SM_FLOATS (128 * 36 + 64 * 36 + 64 * 40 + 128 * 68)
__global__ __launch_bounds__(256, 2) void k_attn(const float* __restrict__ beta) {
    extern __shared__ float sa[];
    float* Qs = sa;                   // [128][36]  (==4 mod 32)
    float* Ks = Qs + 128 * 36;        // [64][36]
    float* Vs = Ks + 64 * 36;         // [64][40]   (==8 mod 32)
    float* Ps = Vs + 64 * 40;         // [128][68]  P staging (warp-private rows)
    int b = blockIdx.x, h = blockIdx.y, qt = blockIdx.z;
    int t = threadIdx.x, w = t >> 5, lane = t & 31;
    int lg = lane >> 2, lr = lane & 3;
    int wr = w * 16;

    const float* qg = g_q + ((size_t)(b * SS + qt * 128)) * CSd + h * Dd;
    #pragma unroll
    for (int idx = t; idx < 128 * 8; idx += 256) {
        int r = idx >> 3, c4 = (idx & 7) * 4;
        float4 v = *(const float4*)&qg[(size_t)r * CSd + c4];
        float4 tv = {to_tf32(v.x), to_tf32(v.y), to_tf32(v.z), to_tf32(v.w)};
        *(float4*)&Qs[r * 36 + c4] = tv;
    }

    const float* kg = g_k + (size_t)(b * SS) * CSd + h * Dd;
    const float* vg = g_v + (size_t)(b * SS) * CSd + h * Dd;
    const float* bias_b = g_bias + ((size_t)h << 20) + (size_t)(qt * 128) * SS;
    const float* beta_b = beta + ((size_t)b << 20) + (size_t)(qt * 128) * SS;

    // prefetch tile 0 into registers
    float4 kf[2], vf[2];
    #pragma unroll
    for (int it = 0; it < 2; it++) {
        int idx = t + it * 256;
        int r = idx >> 3, c4 = (idx & 7) * 4;
        kf[it] = *(const float4*)&kg[(size_t)r * CSd + c4];
        vf[it] = *(const float4*)&vg[(size_t)r * CSd + c4];
    }
    __syncthreads();   // Qs visible

    // hoisted Q fragments (constant across all 16 k-tiles)
    uint32_t qa[4][4];
    #pragma unroll
    for (int kc = 0; kc < 4; kc++) {
        const float* qp = &Qs[(wr + lg) * 36 + kc * 8 + lr];
        qa[kc][0] = FBITS(qp[0]);      qa[kc][1] = FBITS(qp[8 * 36]);
        qa[kc][2] = FBITS(qp[4]);      qa[kc][3] = FBITS(qp[8 * 36 + 4]);
    }

    float O[4][4];
    #pragma unroll
    for (int dn = 0; dn < 4; dn++)
        #pragma unroll
        for (int j = 0; j < 4; j++) O[dn][j] = 0.f;
    float l0 = 0.f, l1 = 0.f;

    for (int kt = 0; kt < 16; kt++) {
        // commit prefetched K/V tile to smem (tf32-converted)
        #pragma unroll
        for (int it = 0; it < 2; it++) {
            int idx = t + it * 256;
            int r = idx >> 3, c4 = (idx & 7) * 4;
            float4 tk = {to_tf32(kf[it].x), to_tf32(kf[it].y), to_tf32(kf[it].z), to_tf32(kf[it].w)};
            float4 tv = {to_tf32(vf[it].x), to_tf32(vf[it].y), to_tf32(vf[it].z), to_tf32(vf[it].w)};
            *(float4*)&Ks[r * 36 + c4] = tk;
            *(float4*)&Vs[r * 40 + c4] = tv;
        }
        __syncthreads();
        // prefetch next tile (hidden behind compute; last iter re-reads tile 15, L2-hot)
        {
            int ktn = (kt < 15) ? (kt + 1) : 15;
            #pragma unroll
            for (int it = 0; it < 2; it++) {
                int idx = t + it * 256;
                int r = idx >> 3, c4 = (idx & 7) * 4;
                kf[it] = *(const float4*)&kg[(size_t)(ktn * 64 + r) * CSd + c4];
                vf[it] = *(const float4*)&vg[(size_t)(ktn * 64 + r) * CSd + c4];
            }
        }

        const float* bp0 = bias_b + (size_t)(wr + lg) * SS + kt * 64 + 2 * lr;
        const float* tp0 = beta_b + (size_t)(wr + lg) * SS + kt * 64 + 2 * lr;
        float ls0 = 0.f, ls1 = 0.f;
        #pragma unroll
        for (int nt = 0; nt < 8; nt++) {
            float S[4] = {0.f, 0.f, 0.f, 0.f};
            #pragma unroll
            for (int kc = 0; kc < 4; kc++) {
                const float* kp = &Ks[(nt * 8 + lg) * 36 + kc * 8 + lr];
                uint32_t b0 = FBITS(kp[0]), b1 = FBITS(kp[4]);
                mma_tf32(S, qa[kc][0], qa[kc][1], qa[kc][2], qa[kc][3], b0, b1);
            }
            float2 x0 = *(const float2*)(bp0 + nt * 8);
            float2 y0 = *(const float2*)(tp0 + nt * 8);
            float2 x1 = *(const float2*)(bp0 + 8 * SS + nt * 8);
            float2 y1 = *(const float2*)(tp0 + 8 * SS + nt * 8);
            float p0 = to_tf32(__expf(fmaxf(S[0] + x0.x + y0.x, -80.f)));
            float p1 = to_tf32(__expf(fmaxf(S[1] + x0.y + y0.y, -80.f)));
            float p2 = to_tf32(__expf(fmaxf(S[2] + x1.x + y1.x, -80.f)));
            float p3 = to_tf32(__expf(fmaxf(S[3] + x1.y + y1.y, -80.f)));
            ls0 += p0 + p1;  ls1 += p2 + p3;
            float* pb = &Ps[(wr + lg) * 68 + nt * 8 + 2 * lr];
            pb[0] = p0;  pb[1] = p1;
            pb[8 * 68] = p2;  pb[8 * 68 + 1] = p3;
        }
        l0 += ls0;  l1 += ls1;
        __syncwarp();
        // ---- O += P @ V ----
        #pragma unroll
        for (int kc = 0; kc < 8; kc++) {
            const float* pp = &Ps[(wr + lg) * 68 + kc * 8 + lr];
            uint32_t a0 = FBITS(pp[0]), a1 = FBITS(pp[8 * 68]);
            uint32_t a2 = FBITS(pp[4]), a3 = FBITS(pp[8 * 68 + 4]);
            #pragma unroll
            for (int dn = 0; dn < 4; dn++) {
                const float* vp = &Vs[(kc * 8 + lr) * 40 + dn * 8 + lg];
                uint32_t b0 = FBITS(vp[0]), b1 = FBITS(vp[4 * 40]);
                mma_tf32(O[dn], a0, a1, a2, a3, b0, b1);
            }
        }
        __syncthreads();   // protect Ks/Vs before next commit
    }

    // full-row denominators: sum partial l across the quad (cols are split over lr)
    l0 += __shfl_xor_sync(0xffffffffu, l0, 1);
    l0 += __shfl_xor_sync(0xffffffffu, l0, 2);
    l1 += __shfl_xor_sync(0xffffffffu, l1, 1);
    l1 += __shfl_xor_sync(0xffffffffu, l1, 2);
    float inv0 = 1.0f / l0, inv1 = 1.0f / l1;
    float* og = g_attno + ((size_t)(b * SS + qt * 128)) * CSd + h * Dd;
    #pragma unroll
    for (int dn = 0; dn < 4; dn++) {
        int col = dn * 8 + 2 * lr;
        int r0 = wr + lg;
        float2 v0 = {O[dn][0] * inv0, O[dn][1] * inv0};
        float2 v1 = {O[dn][2] * inv1, O[dn][3] * inv1};
        *(float2*)&og[(size_t)r0 * CSd + col] = v0;
        *(float2*)&og[(size_t)(r0 + 8) * CSd + col] = v1;
    }
}

// ---------------- 7) out projection + bias + gate (tf32 mma) ----------------
// grid (6, 16), block 256
__global__ __launch_bounds__(256) void k_gemm_out(const float* __restrict__ wo,
                                                  const float* __restrict__ bo,
                                                  float* __restrict__ out) {
    __shared__ float As[128 * 36];
    __shared__ float Ws[32 * 136];
    const float* A = g_attno;
    int t = threadIdx.x, w = t >> 5, lane = t & 31;
    int lg = lane >> 2, lr = lane & 3;
    int m0 = blockIdx.y * 128, n0 = blockIdx.x * 128;
    int wm = (w & 3) * 32, wn = (w >> 2) * 64;
    float acc[2][8][4];
    #pragma unroll
    for (int mt = 0; mt < 2; mt++)
        #pragma unroll
        for (int nt = 0; nt < 8; nt++)
            #pragma unroll
            for (int j = 0; j < 4; j++) acc[mt][nt][j] = 0.f;

    for (int k0 = 0; k0 < CSd; k0 += 32) {
        __syncthreads();
        #pragma unroll
        for (int idx = t; idx < 1024; idx += 256) {
            int r = idx >> 3, c4 = (idx & 7) * 4;
            float4 v = *(const float4*)&A[(size_t)(m0 + r) * CSd + k0 + c4];
            float4 tv = {to_tf32(v.x), to_tf32(v.y), to_tf32(v.z), to_tf32(v.w)};
            *(float4*)&As[r * 36 + c4] = tv;
        }
        #pragma unroll
        for (int idx = t; idx < 1024; idx += 256) {
            int r = idx >> 5, c4 = (idx & 31) * 4;
            float4 v = *(const float4*)&wo[(size_t)(k0 + r) * CSd + n0 + c4];
            float4 tv = {to_tf32(v.x), to_tf32(v.y), to_tf32(v.z), to_tf32(v.w)};
            *(float4*)&Ws[r * 136 + c4] = tv;
        }
        __syncthreads();
        #pragma unroll
        for (int kc = 0; kc < 4; kc++) {
            uint32_t a[2][4];
            #pragma unroll
            for (int mt = 0; mt < 2; mt++) {
                const float* ap = &As[(wm + mt * 16 + lg) * 36 + kc * 8 + lr];
                a[mt][0] = FBITS(ap[0]);       a[mt][1] = FBITS(ap[8 * 36]);
                a[mt][2] = FBITS(ap[4]);       a[mt][3] = FBITS(ap[8 * 36 + 4]);
            }
            #pragma unroll
            for (int nt = 0; nt < 8; nt++) {
                const float* wp = &Ws[(kc * 8 + lr) * 136 + wn + nt * 8 + lg];
                uint32_t b0 = FBITS(wp[0]), b1 = FBITS(wp[4 * 136]);
                mma_tf32(acc[0][nt], a[0][0], a[0][1], a[0][2], a[0][3], b0, b1);
                mma_tf32(acc[1][nt], a[1][0], a[1][1], a[1][2], a[1][3], b0, b1);
            }
        }
    }
    #pragma unroll
    for (int mt = 0; mt < 2; mt++)
        #pragma unroll
        for (int nt = 0; nt < 8; nt++) {
            int row = m0 + wm + mt * 16 + lg;
            int col = n0 + wn + nt * 8 + 2 * lr;
            int bidx = row >> 10;
            const float* gate = g_emb + bidx * 3 * CSd + 2 * CSd;
            float gb0 = gate[col], gb1 = gate[col + 1];
            float bb0 = bo[col], bb1 = bo[col + 1];
            float2 v0 = {(acc[mt][nt][0] + bb0) * gb0, (acc[mt][nt][1] + bb1) * gb1};
            float2 v1 = {(acc[mt][nt][2] + bb0) * gb0, (acc[mt][nt][3] + bb1) * gb1};
            *(float2*)&out[(size_t)row * CSd + col] = v0;
            *(float2*)&out[(size_t)(row + 8) * CSd + col] = v1;
        }
}

// ---------------- launch (fork k_bias onto a side stream, join before attn) ----------------
extern "C" void kernel_launch(void* const* d_in, const int* in_sizes, int n_in,
                              void* d_out, int out_size) {
    const float* bs      = (const float*)d_in[0];
    const float* z       = (const float*)d_in[1];
    const float* t       = (const float*)d_in[2];
    const float* beta    = (const float*)d_in[3];
    const int*   z_mask  = (const int*)d_in[4];
    const float* w_adaln = (const float*)d_in[5];
    const float* b_adaln = (const float*)d_in[6];
    const float* ln_z_w  = (const float*)d_in[7];
    const float* ln_z_b  = (const float*)d_in[8];
    const float* w_q     = (const float*)d_in[9];
    const float* w_k     = (const float*)d_in[10];
    const float* w_v     = (const float*)d_in[11];
    const float* w_z     = (const float*)d_in[12];
    const float* rms_q_w = (const float*)d_in[13];
    const float* rms_k_w = (const float*)d_in[14];
    const float* w_o     = (const float*)d_in[15];
    const float* b_o     = (const float*)d_in[16];
    float* out = (float*)d_out;

    static cudaStream_t s_bias = nullptr;
    static cudaEvent_t ev_fork = nullptr, ev_join = nullptr;
    if (s_bias == nullptr) {
        (void)cudaStreamCreateWithFlags(&s_bias, cudaStreamNonBlocking);
        (void)cudaEventCreateWithFlags(&ev_fork, cudaEventDisableTiming);
        (void)cudaEventCreateWithFlags(&ev_join, cudaEventDisableTiming);
        (void)cudaFuncSetAttribute(k_bias, cudaFuncAttributeMaxDynamicSharedMemorySize,
                                   BIAS_SM_FLOATS * (int)sizeof(float));
        (void)cudaFuncSetAttribute(k_attn, cudaFuncAttributeMaxDynamicSharedMemorySize,
                                   ATTN_SM_FLOATS * (int)sizeof(float));
    }

    // fork: bias path is independent of the bs/t path
    (void)cudaEventRecord(ev_fork, 0);
    (void)cudaStreamWaitEvent(s_bias, ev_fork, 0);
    k_bias<<<4096, 256, BIAS_SM_FLOATS * (int)sizeof(float), s_bias>>>(
        z, z_mask, ln_z_w, ln_z_b, w_z);
    (void)cudaEventRecord(ev_join, s_bias);

    // main chain
    k_adaln<<<dim3(18, 2), 128>>>(t, w_adaln, b_adaln);
    k_bsnorm<<<BB * SS, 256>>>(bs);
    k_gemm_qkv<<<dim3(6, 16, 3), 256>>>(w_q, w_k, w_v, rms_q_w, rms_k_w);

    // join, then attention + out-proj
    (void)cudaStreamWaitEvent(0, ev_join, 0);
    k_attn<<<dim3(2, 24, 8), 256, ATTN_SM_FLOATS * (int)sizeof(float)>>>(beta);
    k_gemm_out<<<dim3(6, 16), 256>>>(w_o, b_o, out);
}